// round 6
// baseline (speedup 1.0000x reference)
#include <cuda_runtime.h>
#include <cuda_bf16.h>
#include <cstdint>

// ---------------------------------------------------------------------------
// GCN: h1 = relu((ÂX)W1 + b1); h2 = relu((Âh1)W2 + b2); mean pool; MLP head.
// CSR gather aggregation (atomic-free, L2-tiled), sorted-segment pooling,
// bf16 HMMA GEMMs with 3xBF16 split precision.
// ---------------------------------------------------------------------------

#define MAX_NODES 100000
#define MAX_EDGES 1700000
#define HID 256
#define NGRAPH 2048
#define SCAN_CHUNK 512
#define MAX_SCAN_BLOCKS ((MAX_NODES + SCAN_CHUNK - 1) / SCAN_CHUNK)

__device__ float g_bufA[(size_t)MAX_NODES * HID];
__device__ float g_bufB[(size_t)MAX_NODES * HID];
__device__ float g_dinv[MAX_NODES];
__device__ float g_pool[NGRAPH * HID];
__device__ __nv_bfloat16 g_Whi[256 * 256];
__device__ __nv_bfloat16 g_Wlo[256 * 256];
__device__ int   g_cntI[MAX_NODES];
__device__ int   g_rowptr[MAX_NODES + 1];
__device__ int   g_cursor[MAX_NODES];
__device__ int   g_csrc[MAX_EDGES];
__device__ float g_cnorm[MAX_EDGES];
__device__ int   g_partial[MAX_SCAN_BLOCKS];

// ========================= helpers =========================
__device__ __forceinline__ void split1(float a, __nv_bfloat16& hi, __nv_bfloat16& lo) {
    hi = __float2bfloat16_rn(a);
    lo = __float2bfloat16_rn(a - __bfloat162float(hi));
}

#define LDMX4(R, ADDR)                                                          \
    asm volatile("ldmatrix.sync.aligned.m8n8.x4.shared.b16 {%0,%1,%2,%3}, [%4];" \
                 : "=r"((R)[0]), "=r"((R)[1]), "=r"((R)[2]), "=r"((R)[3])        \
                 : "r"(ADDR))

#define MMA16816(D, A, B0, B1)                                                  \
    asm volatile("mma.sync.aligned.m16n8k16.row.col.f32.bf16.bf16.f32 "          \
                 "{%0,%1,%2,%3}, {%4,%5,%6,%7}, {%8,%9}, {%0,%1,%2,%3};"         \
                 : "+f"((D)[0]), "+f"((D)[1]), "+f"((D)[2]), "+f"((D)[3])        \
                 : "r"((A)[0]), "r"((A)[1]), "r"((A)[2]), "r"((A)[3]),           \
                   "r"(B0), "r"(B1))

// ===================== CSR construction =====================
__global__ void k_zero_cnt(int* cnt, int n) {
    int i = blockIdx.x * blockDim.x + threadIdx.x;
    if (i < n) cnt[i] = 0;
}
__global__ void k_count(const int* __restrict__ dst, int* __restrict__ cnt, int nE) {
    int i = blockIdx.x * blockDim.x + threadIdx.x;
    if (i < nE) atomicAdd(&cnt[dst[i]], 1);
}
__global__ void k_dinv(const int* __restrict__ cnt, float* __restrict__ dinv, int n) {
    int i = blockIdx.x * blockDim.x + threadIdx.x;
    if (i < n) dinv[i] = rsqrtf((float)(cnt[i] + 1));
}

// ---- 3-phase scan ----
__global__ void k_scan_p1(const int* __restrict__ cnt, int* __restrict__ partial, int n) {
    __shared__ int s[256];
    int b = blockIdx.x, t = threadIdx.x;
    int base = b * SCAN_CHUNK;
    int i0 = base + t, i1 = base + 256 + t;
    int v = 0;
    if (i0 < n) v += cnt[i0];
    if (i1 < n) v += cnt[i1];
    s[t] = v;
    __syncthreads();
    #pragma unroll
    for (int off = 128; off > 0; off >>= 1) {
        if (t < off) s[t] += s[t + off];
        __syncthreads();
    }
    if (t == 0) partial[b] = s[0];
}
__global__ void k_scan_p2(int* __restrict__ partial, int nb) {
    __shared__ int s[256];
    int t = threadIdx.x;
    int v = (t < nb) ? partial[t] : 0;
    s[t] = v;
    __syncthreads();
    #pragma unroll
    for (int off = 1; off < 256; off <<= 1) {
        int u = (t >= off) ? s[t - off] : 0;
        __syncthreads();
        s[t] += u;
        __syncthreads();
    }
    if (t < nb) partial[t] = s[t] - v;
}
__global__ void k_scan_p3(const int* __restrict__ cnt, const int* __restrict__ partial,
                          int* __restrict__ rowptr, int* __restrict__ cursor, int n) {
    __shared__ int s[256];
    int b = blockIdx.x, t = threadIdx.x;
    int base = b * SCAN_CHUNK;
    int i0 = base + 2 * t, i1 = i0 + 1;
    int c0 = (i0 < n) ? cnt[i0] : 0;
    int c1 = (i1 < n) ? cnt[i1] : 0;
    int pairSum = c0 + c1;
    s[t] = pairSum;
    __syncthreads();
    #pragma unroll
    for (int off = 1; off < 256; off <<= 1) {
        int u = (t >= off) ? s[t - off] : 0;
        __syncthreads();
        s[t] += u;
        __syncthreads();
    }
    int pre = s[t] - pairSum + partial[b];
    if (i0 < n) { rowptr[i0] = pre; cursor[i0] = pre; if (i0 == n - 1) rowptr[n] = pre + c0; }
    if (i1 < n) { rowptr[i1] = pre + c0; cursor[i1] = pre + c0; if (i1 == n - 1) rowptr[n] = pre + c0 + c1; }
}

__global__ void k_fill(const int* __restrict__ src, const int* __restrict__ dst,
                       const float* __restrict__ dinv, int* __restrict__ cursor,
                       int* __restrict__ csrc, float* __restrict__ cnorm, int nE) {
    int i = blockIdx.x * blockDim.x + threadIdx.x;
    if (i >= nE) return;
    int s = src[i], d = dst[i];
    int pos = atomicAdd(&cursor[d], 1);
    csrc[pos] = s;
    cnorm[pos] = dinv[s] * dinv[d];
}

// ===================== CSR gather aggregation =====================
__global__ __launch_bounds__(256)
void k_gather128(const float* __restrict__ X, const int* __restrict__ rowptr,
                 const int* __restrict__ csrc, const float* __restrict__ cnorm,
                 const float* __restrict__ dinv, float* __restrict__ OUT, int n) {
    int node = (blockIdx.x * blockDim.x + threadIdx.x) >> 5;
    if (node >= n) return;
    int lane = threadIdx.x & 31;
    float di = dinv[node];
    const float4* Xv = (const float4*)X;
    float4 a = Xv[(size_t)node * 32 + lane];
    float s2 = di * di;
    a.x *= s2; a.y *= s2; a.z *= s2; a.w *= s2;
    int e = rowptr[node], e1 = rowptr[node + 1];
    for (; e + 2 <= e1; e += 2) {
        int   s0 = csrc[e],  s1 = csrc[e + 1];
        float n0 = cnorm[e], n1 = cnorm[e + 1];
        float4 v0 = Xv[(size_t)s0 * 32 + lane];
        float4 v1 = Xv[(size_t)s1 * 32 + lane];
        a.x += n0 * v0.x + n1 * v1.x;
        a.y += n0 * v0.y + n1 * v1.y;
        a.z += n0 * v0.z + n1 * v1.z;
        a.w += n0 * v0.w + n1 * v1.w;
    }
    if (e < e1) {
        int s0 = csrc[e]; float n0 = cnorm[e];
        float4 v0 = Xv[(size_t)s0 * 32 + lane];
        a.x += n0 * v0.x; a.y += n0 * v0.y; a.z += n0 * v0.z; a.w += n0 * v0.w;
    }
    __stcs(&((float4*)OUT)[(size_t)node * 32 + lane], a);
}

// 256-wide gather, column-tiled: processes 128 cols per pass (col4Off in {0,32}).
// Keeps the random-read working set at 51 MB -> L2-resident.
__global__ __launch_bounds__(256)
void k_gather256_half(const float* __restrict__ X, const int* __restrict__ rowptr,
                      const int* __restrict__ csrc, const float* __restrict__ cnorm,
                      const float* __restrict__ dinv, float* __restrict__ OUT,
                      int n, int col4Off) {
    int node = (blockIdx.x * blockDim.x + threadIdx.x) >> 5;
    if (node >= n) return;
    int lane = threadIdx.x & 31;
    float di = dinv[node];
    const float4* Xv = (const float4*)X;
    size_t base = (size_t)node * 64 + col4Off + lane;
    float4 a = Xv[base];
    float s2 = di * di;
    a.x *= s2; a.y *= s2; a.z *= s2; a.w *= s2;
    int e = rowptr[node], e1 = rowptr[node + 1];
    for (; e + 2 <= e1; e += 2) {
        int   s0 = csrc[e],  s1 = csrc[e + 1];
        float n0 = cnorm[e], n1 = cnorm[e + 1];
        float4 v0 = Xv[(size_t)s0 * 64 + col4Off + lane];
        float4 v1 = Xv[(size_t)s1 * 64 + col4Off + lane];
        a.x += n0 * v0.x + n1 * v1.x;
        a.y += n0 * v0.y + n1 * v1.y;
        a.z += n0 * v0.z + n1 * v1.z;
        a.w += n0 * v0.w + n1 * v1.w;
    }
    if (e < e1) {
        int s0 = csrc[e]; float n0 = cnorm[e];
        float4 v0 = Xv[(size_t)s0 * 64 + col4Off + lane];
        a.x += n0 * v0.x; a.y += n0 * v0.y; a.z += n0 * v0.z; a.w += n0 * v0.w;
    }
    __stcs(&((float4*)OUT)[base], a);
}

// ================= W prep: fp32 [K][256] -> bf16 hi/lo [256][K] =============
__global__ void k_prep_W(const float* __restrict__ W,
                         __nv_bfloat16* __restrict__ Whi,
                         __nv_bfloat16* __restrict__ Wlo, int K) {
    int idx = blockIdx.x * blockDim.x + threadIdx.x;
    if (idx >= K * 256) return;
    int n = idx / K, k = idx % K;
    float v = W[(size_t)k * 256 + n];
    __nv_bfloat16 hi, lo;
    split1(v, hi, lo);
    Whi[idx] = hi;
    Wlo[idx] = lo;
}

// ===================== tensor-core GEMM (M x K) @ (K x 256) =================
#define BM 128
#define BN 128
#define BK 32
#define LDS_PAD 40

__global__ __launch_bounds__(256, 2)
void k_gemm_mma(const float* __restrict__ A,
                const __nv_bfloat16* __restrict__ Bhi,
                const __nv_bfloat16* __restrict__ Blo,
                const float* __restrict__ bias, float* __restrict__ C,
                int M, int K) {
    __shared__ __align__(16) __nv_bfloat16 sAh[BM * LDS_PAD];
    __shared__ __align__(16) __nv_bfloat16 sAl[BM * LDS_PAD];
    __shared__ __align__(16) __nv_bfloat16 sBh[BN * LDS_PAD];
    __shared__ __align__(16) __nv_bfloat16 sBl[BN * LDS_PAD];

    const int tid = threadIdx.x;
    const int wid = tid >> 5, lane = tid & 31;
    const int warpM = wid & 3;
    const int warpN = wid >> 2;
    const int rowBase = blockIdx.y * BM;
    const int colBase = blockIdx.x * BN;

    float acc[2][8][4];
    #pragma unroll
    for (int i = 0; i < 2; i++)
        #pragma unroll
        for (int j = 0; j < 8; j++)
            #pragma unroll
            for (int q = 0; q < 4; q++) acc[i][j][q] = 0.f;

    const int aRow = warpM * 32 + (lane & 15);
    const int aK   = (lane >> 4) * 8;
    const int bRowBase = warpN * 64 + (lane & 7) + ((lane >> 4) << 3);
    const int bK   = ((lane >> 3) & 1) * 8;

    uint32_t sAh_b = (uint32_t)__cvta_generic_to_shared(sAh);
    uint32_t sAl_b = (uint32_t)__cvta_generic_to_shared(sAl);
    uint32_t sBh_b = (uint32_t)__cvta_generic_to_shared(sBh);
    uint32_t sBl_b = (uint32_t)__cvta_generic_to_shared(sBl);

    for (int k0 = 0; k0 < K; k0 += BK) {
        {
            int r0 = tid >> 3;
            int k4 = (tid & 7) * 4;
            #pragma unroll
            for (int it = 0; it < 4; ++it) {
                int r = r0 + it * 32;
                int gr = rowBase + r;
                float4 v = make_float4(0.f, 0.f, 0.f, 0.f);
                if (gr < M) v = *(const float4*)(A + (size_t)gr * K + k0 + k4);
                __nv_bfloat16 h0, l0, h1, l1, h2, l2, h3, l3;
                split1(v.x, h0, l0); split1(v.y, h1, l1);
                split1(v.z, h2, l2); split1(v.w, h3, l3);
                __nv_bfloat162 H0 = __nv_bfloat162(h0, h1), H1 = __nv_bfloat162(h2, h3);
                __nv_bfloat162 L0 = __nv_bfloat162(l0, l1), L1 = __nv_bfloat162(l2, l3);
                int off = r * LDS_PAD + k4;
                *(uint2*)&sAh[off] = make_uint2(*(uint32_t*)&H0, *(uint32_t*)&H1);
                *(uint2*)&sAl[off] = make_uint2(*(uint32_t*)&L0, *(uint32_t*)&L1);
            }
        }
        {
            #pragma unroll
            for (int it = 0; it < 2; ++it) {
                int i = tid + it * 256;
                int n = i >> 2;
                int kq = (i & 3) * 8;
                int off = n * LDS_PAD + kq;
                const size_t g = (size_t)(colBase + n) * K + k0 + kq;
                *(uint4*)&sBh[off] = *(const uint4*)(Bhi + g);
                *(uint4*)&sBl[off] = *(const uint4*)(Blo + g);
            }
        }
        __syncthreads();

        #pragma unroll
        for (int kk = 0; kk < BK; kk += 16) {
            uint32_t aH[2][4], aL[2][4];
            #pragma unroll
            for (int mi = 0; mi < 2; ++mi) {
                uint32_t o = (uint32_t)((aRow + mi * 16) * LDS_PAD + kk + aK) * 2;
                LDMX4(aH[mi], sAh_b + o);
                LDMX4(aL[mi], sAl_b + o);
            }
            #pragma unroll
            for (int nj = 0; nj < 4; ++nj) {
                uint32_t bH[4], bL[4];
                uint32_t o = (uint32_t)((bRowBase + nj * 16) * LDS_PAD + kk + bK) * 2;
                LDMX4(bH, sBh_b + o);
                LDMX4(bL, sBl_b + o);
                #pragma unroll
                for (int mi = 0; mi < 2; ++mi) {
                    MMA16816(acc[mi][nj * 2 + 0], aH[mi], bH[0], bH[1]);
                    MMA16816(acc[mi][nj * 2 + 1], aH[mi], bH[2], bH[3]);
                    MMA16816(acc[mi][nj * 2 + 0], aH[mi], bL[0], bL[1]);
                    MMA16816(acc[mi][nj * 2 + 1], aH[mi], bL[2], bL[3]);
                    MMA16816(acc[mi][nj * 2 + 0], aL[mi], bH[0], bH[1]);
                    MMA16816(acc[mi][nj * 2 + 1], aL[mi], bH[2], bH[3]);
                }
            }
        }
        __syncthreads();
    }

    const int erow = rowBase + warpM * 32 + (lane >> 2);
    const int ecol = colBase + warpN * 64 + (lane & 3) * 2;
    #pragma unroll
    for (int mi = 0; mi < 2; ++mi) {
        int r0 = erow + mi * 16;
        #pragma unroll
        for (int nj = 0; nj < 8; ++nj) {
            int c = ecol + nj * 8;
            float b0 = bias[c], b1 = bias[c + 1];
            if (r0 < M) {
                float2 v;
                v.x = fmaxf(acc[mi][nj][0] + b0, 0.f);
                v.y = fmaxf(acc[mi][nj][1] + b1, 0.f);
                *(float2*)(C + (size_t)r0 * 256 + c) = v;
            }
            if (r0 + 8 < M) {
                float2 v;
                v.x = fmaxf(acc[mi][nj][2] + b0, 0.f);
                v.y = fmaxf(acc[mi][nj][3] + b1, 0.f);
                *(float2*)(C + (size_t)(r0 + 8) * 256 + c) = v;
            }
        }
    }
}

// ============ pooling: sorted-segment mean, one warp per graph =============
__global__ __launch_bounds__(256)
void k_pool_seg(const float* __restrict__ H, const int* __restrict__ batch,
                float* __restrict__ pool, int n) {
    int g = (blockIdx.x * blockDim.x + threadIdx.x) >> 5;
    if (g >= NGRAPH) return;
    int lane = threadIdx.x & 31;
    // lower_bound(batch, g) and lower_bound(batch, g+1)
    int lo = 0, hi = n;
    while (lo < hi) { int mid = (lo + hi) >> 1; if (batch[mid] < g) lo = mid + 1; else hi = mid; }
    int start = lo;
    hi = n;
    while (lo < hi) { int mid = (lo + hi) >> 1; if (batch[mid] < g + 1) lo = mid + 1; else hi = mid; }
    int end = lo;

    float4 a0 = make_float4(0.f, 0.f, 0.f, 0.f);
    float4 a1 = make_float4(0.f, 0.f, 0.f, 0.f);
    const float4* Hv = (const float4*)H;
    for (int i = start; i < end; ++i) {
        size_t b = (size_t)i * 64 + lane;
        float4 v0 = Hv[b], v1 = Hv[b + 32];
        a0.x += v0.x; a0.y += v0.y; a0.z += v0.z; a0.w += v0.w;
        a1.x += v1.x; a1.y += v1.y; a1.z += v1.z; a1.w += v1.w;
    }
    float inv = (end > start) ? 1.0f / (float)(end - start) : 0.f;
    a0.x *= inv; a0.y *= inv; a0.z *= inv; a0.w *= inv;
    a1.x *= inv; a1.y *= inv; a1.z *= inv; a1.w *= inv;
    size_t pb = (size_t)g * 64 + lane;
    ((float4*)pool)[pb] = a0;
    ((float4*)pool)[pb + 32] = a1;
}

// ================================ MLP head =================================
__global__ void k_mlp(const float* __restrict__ pool,
                      const float* __restrict__ Wf1, const float* __restrict__ bf1,
                      const float* __restrict__ Wf2, const float* __restrict__ bf2,
                      float* __restrict__ out) {
    int g = blockIdx.x;
    __shared__ float p[HID];
    __shared__ float red[128];
    int t = threadIdx.x;
    p[t]       = pool[g * HID + t];
    p[t + 128] = pool[g * HID + 128 + t];
    __syncthreads();
    float acc = bf1[t];
    #pragma unroll 8
    for (int k = 0; k < HID; k++) acc += p[k] * Wf1[k * 128 + t];
    red[t] = fmaxf(acc, 0.f) * Wf2[t];
    __syncthreads();
    for (int s = 64; s > 0; s >>= 1) {
        if (t < s) red[t] += red[t + s];
        __syncthreads();
    }
    if (t == 0) out[g] = red[0] + bf2[0];
}

// ---------------------------------------------------------------------------
extern "C" void kernel_launch(void* const* d_in, const int* in_sizes, int n_in,
                              void* d_out, int out_size) {
    const float* x   = (const float*)d_in[0];
    const int*   ei  = (const int*)d_in[1];
    const int*   bat = (const int*)d_in[2];
    const float* W1  = (const float*)d_in[3];
    const float* b1  = (const float*)d_in[4];
    const float* W2  = (const float*)d_in[5];
    const float* b2  = (const float*)d_in[6];
    const float* Wf1 = (const float*)d_in[7];
    const float* bf1 = (const float*)d_in[8];
    const float* Wf2 = (const float*)d_in[9];
    const float* bf2 = (const float*)d_in[10];
    float* out = (float*)d_out;

    int n  = in_sizes[0] / 128;
    int nE = in_sizes[1] / 2;
    const int* src = ei;
    const int* dst = ei + nE;

    float *bufA, *bufB, *dinv, *pool;
    __nv_bfloat16 *Whi, *Wlo;
    int *cntI, *rowptr, *cursor, *csrc, *partial;
    float *cnorm;
    cudaGetSymbolAddress((void**)&bufA, g_bufA);
    cudaGetSymbolAddress((void**)&bufB, g_bufB);
    cudaGetSymbolAddress((void**)&dinv, g_dinv);
    cudaGetSymbolAddress((void**)&pool, g_pool);
    cudaGetSymbolAddress((void**)&Whi,  g_Whi);
    cudaGetSymbolAddress((void**)&Wlo,  g_Wlo);
    cudaGetSymbolAddress((void**)&cntI, g_cntI);
    cudaGetSymbolAddress((void**)&rowptr, g_rowptr);
    cudaGetSymbolAddress((void**)&cursor, g_cursor);
    cudaGetSymbolAddress((void**)&csrc, g_csrc);
    cudaGetSymbolAddress((void**)&cnorm, g_cnorm);
    cudaGetSymbolAddress((void**)&partial, g_partial);

    // --- CSR build ---
    int nb = (n + SCAN_CHUNK - 1) / SCAN_CHUNK;
    k_zero_cnt<<<(n + 255) / 256, 256>>>(cntI, n);
    k_count<<<(nE + 255) / 256, 256>>>(dst, cntI, nE);
    k_dinv<<<(n + 255) / 256, 256>>>(cntI, dinv, n);
    k_scan_p1<<<nb, 256>>>(cntI, partial, n);
    k_scan_p2<<<1, 256>>>(partial, nb);
    k_scan_p3<<<nb, 256>>>(cntI, partial, rowptr, cursor, n);
    k_fill<<<(nE + 255) / 256, 256>>>(src, dst, dinv, cursor, csrc, cnorm, nE);

    dim3 gemmGrid(2, (n + BM - 1) / BM);
    unsigned gatherBlocks = (unsigned)(((long)n * 32 + 255) / 256);

    // --- layer 1 ---
    k_gather128<<<gatherBlocks, 256>>>(x, rowptr, csrc, cnorm, dinv, bufA, n);
    k_prep_W<<<(128 * 256 + 255) / 256, 256>>>(W1, Whi, Wlo, 128);
    k_gemm_mma<<<gemmGrid, 256>>>(bufA, Whi, Wlo, b1, bufB, n, 128);

    // --- layer 2 (gather column-tiled: 2 passes, L2-resident working set) ---
    k_gather256_half<<<gatherBlocks, 256>>>(bufB, rowptr, csrc, cnorm, dinv, bufA, n, 0);
    k_gather256_half<<<gatherBlocks, 256>>>(bufB, rowptr, csrc, cnorm, dinv, bufA, n, 32);
    k_prep_W<<<(256 * 256 + 255) / 256, 256>>>(W2, Whi, Wlo, 256);
    k_gemm_mma<<<gemmGrid, 256>>>(bufA, Whi, Wlo, b2, bufB, n, 256);

    // --- pooling + MLP head ---
    {
        unsigned poolBlocks = (unsigned)(((long)NGRAPH * 32 + 255) / 256);
        k_pool_seg<<<poolBlocks, 256>>>(bufB, bat, pool, n);
    }
    k_mlp<<<NGRAPH, 128>>>(pool, Wf1, bf1, Wf2, bf2, out);
}

// round 7
// speedup vs baseline: 1.0965x; 1.0965x over previous
#include <cuda_runtime.h>
#include <cuda_bf16.h>
#include <cuda_fp16.h>
#include <cstdint>

// ---------------------------------------------------------------------------
// GCN: h1 = relu((ÂX)W1 + b1); h2 = relu((Âh1)W2 + b2); mean pool; MLP head.
// CSR gather aggregation with fp16 gather operands (fp32 accumulate),
// sorted-segment pooling, bf16 HMMA GEMMs with 3xBF16 split precision.
// ---------------------------------------------------------------------------

#define MAX_NODES 100000
#define MAX_EDGES 1700000
#define HID 256
#define NGRAPH 2048
#define SCAN_CHUNK 512
#define MAX_SCAN_BLOCKS ((MAX_NODES + SCAN_CHUNK - 1) / SCAN_CHUNK)

__device__ float  g_bufA[(size_t)MAX_NODES * HID];   // agg (fp32, GEMM input)
__device__ float  g_bufB[(size_t)MAX_NODES * HID];   // h2 (fp32)
__device__ __half g_h1h[(size_t)MAX_NODES * HID];    // h1 (fp16)
__device__ __half g_xh[(size_t)MAX_NODES * 128];     // x (fp16 copy)
__device__ float  g_dinv[MAX_NODES];
__device__ float  g_pool[NGRAPH * HID];
__device__ __nv_bfloat16 g_Whi[256 * 256];
__device__ __nv_bfloat16 g_Wlo[256 * 256];
__device__ int    g_cntI[MAX_NODES];
__device__ int    g_rowptr[MAX_NODES + 1];
__device__ int    g_cursor[MAX_NODES];
__device__ int    g_csrc[MAX_EDGES];
__device__ float  g_cnorm[MAX_EDGES];
__device__ int    g_partial[MAX_SCAN_BLOCKS];

// ========================= helpers =========================
__device__ __forceinline__ void split1(float a, __nv_bfloat16& hi, __nv_bfloat16& lo) {
    hi = __float2bfloat16_rn(a);
    lo = __float2bfloat16_rn(a - __bfloat162float(hi));
}

#define LDMX4(R, ADDR)                                                          \
    asm volatile("ldmatrix.sync.aligned.m8n8.x4.shared.b16 {%0,%1,%2,%3}, [%4];" \
                 : "=r"((R)[0]), "=r"((R)[1]), "=r"((R)[2]), "=r"((R)[3])        \
                 : "r"(ADDR))

#define MMA16816(D, A, B0, B1)                                                  \
    asm volatile("mma.sync.aligned.m16n8k16.row.col.f32.bf16.bf16.f32 "          \
                 "{%0,%1,%2,%3}, {%4,%5,%6,%7}, {%8,%9}, {%0,%1,%2,%3};"         \
                 : "+f"((D)[0]), "+f"((D)[1]), "+f"((D)[2]), "+f"((D)[3])        \
                 : "r"((A)[0]), "r"((A)[1]), "r"((A)[2]), "r"((A)[3]),           \
                   "r"(B0), "r"(B1))

// ===================== CSR construction =====================
__global__ void k_zero_cnt(int* cnt, int n) {
    int i = blockIdx.x * blockDim.x + threadIdx.x;
    if (i < n) cnt[i] = 0;
}
__global__ void k_count(const int* __restrict__ dst, int* __restrict__ cnt, int nE) {
    int i = blockIdx.x * blockDim.x + threadIdx.x;
    if (i < nE) atomicAdd(&cnt[dst[i]], 1);
}
__global__ void k_dinv(const int* __restrict__ cnt, float* __restrict__ dinv, int n) {
    int i = blockIdx.x * blockDim.x + threadIdx.x;
    if (i < n) dinv[i] = rsqrtf((float)(cnt[i] + 1));
}

__global__ void k_scan_p1(const int* __restrict__ cnt, int* __restrict__ partial, int n) {
    __shared__ int s[256];
    int b = blockIdx.x, t = threadIdx.x;
    int base = b * SCAN_CHUNK;
    int i0 = base + t, i1 = base + 256 + t;
    int v = 0;
    if (i0 < n) v += cnt[i0];
    if (i1 < n) v += cnt[i1];
    s[t] = v;
    __syncthreads();
    #pragma unroll
    for (int off = 128; off > 0; off >>= 1) {
        if (t < off) s[t] += s[t + off];
        __syncthreads();
    }
    if (t == 0) partial[b] = s[0];
}
__global__ void k_scan_p2(int* __restrict__ partial, int nb) {
    __shared__ int s[256];
    int t = threadIdx.x;
    int v = (t < nb) ? partial[t] : 0;
    s[t] = v;
    __syncthreads();
    #pragma unroll
    for (int off = 1; off < 256; off <<= 1) {
        int u = (t >= off) ? s[t - off] : 0;
        __syncthreads();
        s[t] += u;
        __syncthreads();
    }
    if (t < nb) partial[t] = s[t] - v;
}
__global__ void k_scan_p3(const int* __restrict__ cnt, const int* __restrict__ partial,
                          int* __restrict__ rowptr, int* __restrict__ cursor, int n) {
    __shared__ int s[256];
    int b = blockIdx.x, t = threadIdx.x;
    int base = b * SCAN_CHUNK;
    int i0 = base + 2 * t, i1 = i0 + 1;
    int c0 = (i0 < n) ? cnt[i0] : 0;
    int c1 = (i1 < n) ? cnt[i1] : 0;
    int pairSum = c0 + c1;
    s[t] = pairSum;
    __syncthreads();
    #pragma unroll
    for (int off = 1; off < 256; off <<= 1) {
        int u = (t >= off) ? s[t - off] : 0;
        __syncthreads();
        s[t] += u;
        __syncthreads();
    }
    int pre = s[t] - pairSum + partial[b];
    if (i0 < n) { rowptr[i0] = pre; cursor[i0] = pre; if (i0 == n - 1) rowptr[n] = pre + c0; }
    if (i1 < n) { rowptr[i1] = pre + c0; cursor[i1] = pre + c0; if (i1 == n - 1) rowptr[n] = pre + c0 + c1; }
}

__global__ void k_fill(const int* __restrict__ src, const int* __restrict__ dst,
                       const float* __restrict__ dinv, int* __restrict__ cursor,
                       int* __restrict__ csrc, float* __restrict__ cnorm, int nE) {
    int i = blockIdx.x * blockDim.x + threadIdx.x;
    if (i >= nE) return;
    int s = src[i], d = dst[i];
    int pos = atomicAdd(&cursor[d], 1);
    csrc[pos] = s;
    cnorm[pos] = dinv[s] * dinv[d];
}

// ===================== fp32 -> fp16 conversion =====================
__global__ void k_f2h(const float* __restrict__ X, __half* __restrict__ Xh, long total4) {
    long i = blockIdx.x * (long)blockDim.x + threadIdx.x;
    if (i >= total4) return;
    float4 v = ((const float4*)X)[i];
    __half2 h0 = __floats2half2_rn(v.x, v.y);
    __half2 h1 = __floats2half2_rn(v.z, v.w);
    ((uint2*)Xh)[i] = make_uint2(*(uint32_t*)&h0, *(uint32_t*)&h1);
}

// ===================== CSR gather (fp16 operands, fp32 accum) ===============
__device__ __forceinline__ void acc4h(float4& a, uint2 u, float nm) {
    float2 p0 = __half22float2(*(__half2*)&u.x);
    float2 p1 = __half22float2(*(__half2*)&u.y);
    a.x += nm * p0.x; a.y += nm * p0.y; a.z += nm * p1.x; a.w += nm * p1.y;
}
__device__ __forceinline__ void acc8h(float4& a0, float4& a1, uint4 u, float nm) {
    float2 p0 = __half22float2(*(__half2*)&u.x);
    float2 p1 = __half22float2(*(__half2*)&u.y);
    float2 p2 = __half22float2(*(__half2*)&u.z);
    float2 p3 = __half22float2(*(__half2*)&u.w);
    a0.x += nm * p0.x; a0.y += nm * p0.y; a0.z += nm * p1.x; a0.w += nm * p1.y;
    a1.x += nm * p2.x; a1.y += nm * p2.y; a1.z += nm * p3.x; a1.w += nm * p3.y;
}

// layer 1: self term from fp32 X, neighbors from fp16 Xh (128 cols)
__global__ __launch_bounds__(256)
void k_gather128h(const float* __restrict__ Xf, const __half* __restrict__ Xh,
                  const int* __restrict__ rowptr, const int* __restrict__ csrc,
                  const float* __restrict__ cnorm, const float* __restrict__ dinv,
                  float* __restrict__ OUT, int n) {
    int node = (blockIdx.x * blockDim.x + threadIdx.x) >> 5;
    if (node >= n) return;
    int lane = threadIdx.x & 31;
    float di = dinv[node];
    float s2 = di * di;
    float4 a = ((const float4*)Xf)[(size_t)node * 32 + lane];
    a.x *= s2; a.y *= s2; a.z *= s2; a.w *= s2;
    const uint2* Xv = (const uint2*)Xh;    // 4 halves per chunk, 32 chunks/row
    int e = rowptr[node], e1 = rowptr[node + 1];
    for (; e + 2 <= e1; e += 2) {
        int   s0 = csrc[e],  s1 = csrc[e + 1];
        float n0 = cnorm[e], n1 = cnorm[e + 1];
        uint2 u0 = Xv[(size_t)s0 * 32 + lane];
        uint2 u1 = Xv[(size_t)s1 * 32 + lane];
        acc4h(a, u0, n0);
        acc4h(a, u1, n1);
    }
    if (e < e1) {
        int s0 = csrc[e]; float n0 = cnorm[e];
        acc4h(a, Xv[(size_t)s0 * 32 + lane], n0);
    }
    __stcs(&((float4*)OUT)[(size_t)node * 32 + lane], a);
}

// layer 2: all from fp16 H (256 cols); chunk lane holds cols [8*lane, 8*lane+8)
__global__ __launch_bounds__(256)
void k_gather256h(const __half* __restrict__ H,
                  const int* __restrict__ rowptr, const int* __restrict__ csrc,
                  const float* __restrict__ cnorm, const float* __restrict__ dinv,
                  float* __restrict__ OUT, int n) {
    int node = (blockIdx.x * blockDim.x + threadIdx.x) >> 5;
    if (node >= n) return;
    int lane = threadIdx.x & 31;
    float di = dinv[node];
    float s2 = di * di;
    const uint4* Hv = (const uint4*)H;     // 8 halves per chunk, 32 chunks/row
    float4 a0 = make_float4(0.f, 0.f, 0.f, 0.f);
    float4 a1 = make_float4(0.f, 0.f, 0.f, 0.f);
    acc8h(a0, a1, Hv[(size_t)node * 32 + lane], s2);   // self-loop
    int e = rowptr[node], e1 = rowptr[node + 1];
    for (; e + 2 <= e1; e += 2) {
        int   s0 = csrc[e],  s1 = csrc[e + 1];
        float n0 = cnorm[e], n1 = cnorm[e + 1];
        uint4 u0 = Hv[(size_t)s0 * 32 + lane];
        uint4 u1 = Hv[(size_t)s1 * 32 + lane];
        acc8h(a0, a1, u0, n0);
        acc8h(a0, a1, u1, n1);
    }
    if (e < e1) {
        int s0 = csrc[e]; float n0 = cnorm[e];
        acc8h(a0, a1, Hv[(size_t)s0 * 32 + lane], n0);
    }
    // chunk lane = cols 8*lane..8*lane+7 -> float4 indices 2*lane, 2*lane+1
    __stcs(&((float4*)OUT)[(size_t)node * 64 + 2 * lane], a0);
    __stcs(&((float4*)OUT)[(size_t)node * 64 + 2 * lane + 1], a1);
}

// ================= W prep: fp32 [K][256] -> bf16 hi/lo [256][K] =============
__global__ void k_prep_W(const float* __restrict__ W,
                         __nv_bfloat16* __restrict__ Whi,
                         __nv_bfloat16* __restrict__ Wlo, int K) {
    int idx = blockIdx.x * blockDim.x + threadIdx.x;
    if (idx >= K * 256) return;
    int n = idx / K, k = idx % K;
    float v = W[(size_t)k * 256 + n];
    __nv_bfloat16 hi, lo;
    split1(v, hi, lo);
    Whi[idx] = hi;
    Wlo[idx] = lo;
}

// ===================== tensor-core GEMM (M x K) @ (K x 256) =================
// C = relu(A @ W + bias); writes fp32 to Cf if non-null, else fp16 to Ch.
#define BM 128
#define BN 128
#define BK 32
#define LDS_PAD 40

__global__ __launch_bounds__(256, 2)
void k_gemm_mma(const float* __restrict__ A,
                const __nv_bfloat16* __restrict__ Bhi,
                const __nv_bfloat16* __restrict__ Blo,
                const float* __restrict__ bias,
                float* __restrict__ Cf, __half* __restrict__ Ch,
                int M, int K) {
    __shared__ __align__(16) __nv_bfloat16 sAh[BM * LDS_PAD];
    __shared__ __align__(16) __nv_bfloat16 sAl[BM * LDS_PAD];
    __shared__ __align__(16) __nv_bfloat16 sBh[BN * LDS_PAD];
    __shared__ __align__(16) __nv_bfloat16 sBl[BN * LDS_PAD];

    const int tid = threadIdx.x;
    const int wid = tid >> 5, lane = tid & 31;
    const int warpM = wid & 3;
    const int warpN = wid >> 2;
    const int rowBase = blockIdx.y * BM;
    const int colBase = blockIdx.x * BN;

    float acc[2][8][4];
    #pragma unroll
    for (int i = 0; i < 2; i++)
        #pragma unroll
        for (int j = 0; j < 8; j++)
            #pragma unroll
            for (int q = 0; q < 4; q++) acc[i][j][q] = 0.f;

    const int aRow = warpM * 32 + (lane & 15);
    const int aK   = (lane >> 4) * 8;
    const int bRowBase = warpN * 64 + (lane & 7) + ((lane >> 4) << 3);
    const int bK   = ((lane >> 3) & 1) * 8;

    uint32_t sAh_b = (uint32_t)__cvta_generic_to_shared(sAh);
    uint32_t sAl_b = (uint32_t)__cvta_generic_to_shared(sAl);
    uint32_t sBh_b = (uint32_t)__cvta_generic_to_shared(sBh);
    uint32_t sBl_b = (uint32_t)__cvta_generic_to_shared(sBl);

    for (int k0 = 0; k0 < K; k0 += BK) {
        {
            int r0 = tid >> 3;
            int k4 = (tid & 7) * 4;
            #pragma unroll
            for (int it = 0; it < 4; ++it) {
                int r = r0 + it * 32;
                int gr = rowBase + r;
                float4 v = make_float4(0.f, 0.f, 0.f, 0.f);
                if (gr < M) v = *(const float4*)(A + (size_t)gr * K + k0 + k4);
                __nv_bfloat16 h0, l0, h1, l1, h2, l2, h3, l3;
                split1(v.x, h0, l0); split1(v.y, h1, l1);
                split1(v.z, h2, l2); split1(v.w, h3, l3);
                __nv_bfloat162 H0 = __nv_bfloat162(h0, h1), H1 = __nv_bfloat162(h2, h3);
                __nv_bfloat162 L0 = __nv_bfloat162(l0, l1), L1 = __nv_bfloat162(l2, l3);
                int off = r * LDS_PAD + k4;
                *(uint2*)&sAh[off] = make_uint2(*(uint32_t*)&H0, *(uint32_t*)&H1);
                *(uint2*)&sAl[off] = make_uint2(*(uint32_t*)&L0, *(uint32_t*)&L1);
            }
        }
        {
            #pragma unroll
            for (int it = 0; it < 2; ++it) {
                int i = tid + it * 256;
                int n = i >> 2;
                int kq = (i & 3) * 8;
                int off = n * LDS_PAD + kq;
                const size_t g = (size_t)(colBase + n) * K + k0 + kq;
                *(uint4*)&sBh[off] = *(const uint4*)(Bhi + g);
                *(uint4*)&sBl[off] = *(const uint4*)(Blo + g);
            }
        }
        __syncthreads();

        #pragma unroll
        for (int kk = 0; kk < BK; kk += 16) {
            uint32_t aH[2][4], aL[2][4];
            #pragma unroll
            for (int mi = 0; mi < 2; ++mi) {
                uint32_t o = (uint32_t)((aRow + mi * 16) * LDS_PAD + kk + aK) * 2;
                LDMX4(aH[mi], sAh_b + o);
                LDMX4(aL[mi], sAl_b + o);
            }
            #pragma unroll
            for (int nj = 0; nj < 4; ++nj) {
                uint32_t bH[4], bL[4];
                uint32_t o = (uint32_t)((bRowBase + nj * 16) * LDS_PAD + kk + bK) * 2;
                LDMX4(bH, sBh_b + o);
                LDMX4(bL, sBl_b + o);
                #pragma unroll
                for (int mi = 0; mi < 2; ++mi) {
                    MMA16816(acc[mi][nj * 2 + 0], aH[mi], bH[0], bH[1]);
                    MMA16816(acc[mi][nj * 2 + 1], aH[mi], bH[2], bH[3]);
                    MMA16816(acc[mi][nj * 2 + 0], aH[mi], bL[0], bL[1]);
                    MMA16816(acc[mi][nj * 2 + 1], aH[mi], bL[2], bL[3]);
                    MMA16816(acc[mi][nj * 2 + 0], aL[mi], bH[0], bH[1]);
                    MMA16816(acc[mi][nj * 2 + 1], aL[mi], bH[2], bH[3]);
                }
            }
        }
        __syncthreads();
    }

    const int erow = rowBase + warpM * 32 + (lane >> 2);
    const int ecol = colBase + warpN * 64 + (lane & 3) * 2;
    #pragma unroll
    for (int mi = 0; mi < 2; ++mi) {
        int r0 = erow + mi * 16;
        #pragma unroll
        for (int nj = 0; nj < 8; ++nj) {
            int c = ecol + nj * 8;
            float b0 = bias[c], b1 = bias[c + 1];
            float v00 = fmaxf(acc[mi][nj][0] + b0, 0.f);
            float v01 = fmaxf(acc[mi][nj][1] + b1, 0.f);
            float v10 = fmaxf(acc[mi][nj][2] + b0, 0.f);
            float v11 = fmaxf(acc[mi][nj][3] + b1, 0.f);
            if (Cf) {
                if (r0 < M)     *(float2*)(Cf + (size_t)r0 * 256 + c)       = make_float2(v00, v01);
                if (r0 + 8 < M) *(float2*)(Cf + (size_t)(r0 + 8) * 256 + c) = make_float2(v10, v11);
            } else {
                if (r0 < M)     *(__half2*)(Ch + (size_t)r0 * 256 + c)       = __floats2half2_rn(v00, v01);
                if (r0 + 8 < M) *(__half2*)(Ch + (size_t)(r0 + 8) * 256 + c) = __floats2half2_rn(v10, v11);
            }
        }
    }
}

// ============ pooling: sorted-segment mean, one warp per graph =============
__global__ __launch_bounds__(256)
void k_pool_seg(const float* __restrict__ H, const int* __restrict__ batch,
                float* __restrict__ pool, int n) {
    int g = (blockIdx.x * blockDim.x + threadIdx.x) >> 5;
    if (g >= NGRAPH) return;
    int lane = threadIdx.x & 31;
    int lo = 0, hi = n;
    while (lo < hi) { int mid = (lo + hi) >> 1; if (batch[mid] < g) lo = mid + 1; else hi = mid; }
    int start = lo;
    hi = n;
    while (lo < hi) { int mid = (lo + hi) >> 1; if (batch[mid] < g + 1) lo = mid + 1; else hi = mid; }
    int end = lo;

    float4 a0 = make_float4(0.f, 0.f, 0.f, 0.f);
    float4 a1 = make_float4(0.f, 0.f, 0.f, 0.f);
    const float4* Hv = (const float4*)H;
    for (int i = start; i < end; ++i) {
        size_t b = (size_t)i * 64 + lane;
        float4 v0 = Hv[b], v1 = Hv[b + 32];
        a0.x += v0.x; a0.y += v0.y; a0.z += v0.z; a0.w += v0.w;
        a1.x += v1.x; a1.y += v1.y; a1.z += v1.z; a1.w += v1.w;
    }
    float inv = (end > start) ? 1.0f / (float)(end - start) : 0.f;
    a0.x *= inv; a0.y *= inv; a0.z *= inv; a0.w *= inv;
    a1.x *= inv; a1.y *= inv; a1.z *= inv; a1.w *= inv;
    size_t pb = (size_t)g * 64 + lane;
    ((float4*)pool)[pb] = a0;
    ((float4*)pool)[pb + 32] = a1;
}

// ================================ MLP head =================================
__global__ void k_mlp(const float* __restrict__ pool,
                      const float* __restrict__ Wf1, const float* __restrict__ bf1,
                      const float* __restrict__ Wf2, const float* __restrict__ bf2,
                      float* __restrict__ out) {
    int g = blockIdx.x;
    __shared__ float p[HID];
    __shared__ float red[128];
    int t = threadIdx.x;
    p[t]       = pool[g * HID + t];
    p[t + 128] = pool[g * HID + 128 + t];
    __syncthreads();
    float acc = bf1[t];
    #pragma unroll 8
    for (int k = 0; k < HID; k++) acc += p[k] * Wf1[k * 128 + t];
    red[t] = fmaxf(acc, 0.f) * Wf2[t];
    __syncthreads();
    for (int s = 64; s > 0; s >>= 1) {
        if (t < s) red[t] += red[t + s];
        __syncthreads();
    }
    if (t == 0) out[g] = red[0] + bf2[0];
}

// ---------------------------------------------------------------------------
extern "C" void kernel_launch(void* const* d_in, const int* in_sizes, int n_in,
                              void* d_out, int out_size) {
    const float* x   = (const float*)d_in[0];
    const int*   ei  = (const int*)d_in[1];
    const int*   bat = (const int*)d_in[2];
    const float* W1  = (const float*)d_in[3];
    const float* b1  = (const float*)d_in[4];
    const float* W2  = (const float*)d_in[5];
    const float* b2  = (const float*)d_in[6];
    const float* Wf1 = (const float*)d_in[7];
    const float* bf1 = (const float*)d_in[8];
    const float* Wf2 = (const float*)d_in[9];
    const float* bf2 = (const float*)d_in[10];
    float* out = (float*)d_out;

    int n  = in_sizes[0] / 128;
    int nE = in_sizes[1] / 2;
    const int* src = ei;
    const int* dst = ei + nE;

    float *bufA, *bufB, *dinv, *pool;
    __half *h1h, *xh;
    __nv_bfloat16 *Whi, *Wlo;
    int *cntI, *rowptr, *cursor, *csrc, *partial;
    float *cnorm;
    cudaGetSymbolAddress((void**)&bufA, g_bufA);
    cudaGetSymbolAddress((void**)&bufB, g_bufB);
    cudaGetSymbolAddress((void**)&h1h,  g_h1h);
    cudaGetSymbolAddress((void**)&xh,   g_xh);
    cudaGetSymbolAddress((void**)&dinv, g_dinv);
    cudaGetSymbolAddress((void**)&pool, g_pool);
    cudaGetSymbolAddress((void**)&Whi,  g_Whi);
    cudaGetSymbolAddress((void**)&Wlo,  g_Wlo);
    cudaGetSymbolAddress((void**)&cntI, g_cntI);
    cudaGetSymbolAddress((void**)&rowptr, g_rowptr);
    cudaGetSymbolAddress((void**)&cursor, g_cursor);
    cudaGetSymbolAddress((void**)&csrc, g_csrc);
    cudaGetSymbolAddress((void**)&cnorm, g_cnorm);
    cudaGetSymbolAddress((void**)&partial, g_partial);

    // --- CSR build + x->fp16 ---
    int nb = (n + SCAN_CHUNK - 1) / SCAN_CHUNK;
    k_zero_cnt<<<(n + 255) / 256, 256>>>(cntI, n);
    k_count<<<(nE + 255) / 256, 256>>>(dst, cntI, nE);
    k_dinv<<<(n + 255) / 256, 256>>>(cntI, dinv, n);
    k_scan_p1<<<nb, 256>>>(cntI, partial, n);
    k_scan_p2<<<1, 256>>>(partial, nb);
    k_scan_p3<<<nb, 256>>>(cntI, partial, rowptr, cursor, n);
    k_fill<<<(nE + 255) / 256, 256>>>(src, dst, dinv, cursor, csrc, cnorm, nE);
    {
        long t4 = (long)n * 32;
        k_f2h<<<(unsigned)((t4 + 255) / 256), 256>>>(x, xh, t4);
    }

    dim3 gemmGrid(2, (n + BM - 1) / BM);
    unsigned gatherBlocks = (unsigned)(((long)n * 32 + 255) / 256);

    // --- layer 1: gather(fp16 x) -> fp32 agg; GEMM -> fp16 h1 ---
    k_gather128h<<<gatherBlocks, 256>>>(x, xh, rowptr, csrc, cnorm, dinv, bufA, n);
    k_prep_W<<<(128 * 256 + 255) / 256, 256>>>(W1, Whi, Wlo, 128);
    k_gemm_mma<<<gemmGrid, 256>>>(bufA, Whi, Wlo, b1, nullptr, h1h, n, 128);

    // --- layer 2: gather(fp16 h1) -> fp32 agg; GEMM -> fp32 h2 ---
    k_gather256h<<<gatherBlocks, 256>>>(h1h, rowptr, csrc, cnorm, dinv, bufA, n);
    k_prep_W<<<(256 * 256 + 255) / 256, 256>>>(W2, Whi, Wlo, 256);
    k_gemm_mma<<<gemmGrid, 256>>>(bufA, Whi, Wlo, b2, bufB, nullptr, n, 256);

    // --- pooling + MLP head ---
    {
        unsigned poolBlocks = (unsigned)(((long)NGRAPH * 32 + 255) / 256);
        k_pool_seg<<<poolBlocks, 256>>>(bufB, bat, pool, n);
    }
    k_mlp<<<NGRAPH, 128>>>(pool, Wf1, bf1, Wf2, bf2, out);
}

// round 8
// speedup vs baseline: 1.1059x; 1.0085x over previous
#include <cuda_runtime.h>
#include <cuda_bf16.h>
#include <cuda_fp16.h>
#include <cstdint>

// ---------------------------------------------------------------------------
// GCN: h1 = relu((ÂX)W1 + b1); h2 = relu((Âh1)W2 + b2); mean pool; MLP head.
// CSR gather (fp16 operands, fp32 accum) emitting pre-split bf16 hi/lo agg;
// bf16 HMMA GEMMs (3xBF16 split precision); sorted-segment pooling.
// ---------------------------------------------------------------------------

#define MAX_NODES 100000
#define MAX_EDGES 1700000
#define HID 256
#define NGRAPH 2048
#define SCAN_CHUNK 512
#define MAX_SCAN_BLOCKS ((MAX_NODES + SCAN_CHUNK - 1) / SCAN_CHUNK)

__device__ __nv_bfloat16 g_aggHi[(size_t)MAX_NODES * HID];  // agg hi (GEMM A)
__device__ __nv_bfloat16 g_aggLo[(size_t)MAX_NODES * HID];  // agg lo
__device__ float  g_bufB[(size_t)MAX_NODES * HID];          // h2 (fp32)
__device__ __half g_h1h[(size_t)MAX_NODES * HID];           // h1 (fp16)
__device__ __half g_xh[(size_t)MAX_NODES * 128];            // x (fp16)
__device__ float  g_dinv[MAX_NODES];
__device__ float  g_pool[NGRAPH * HID];
__device__ __nv_bfloat16 g_Whi[256 * 256];
__device__ __nv_bfloat16 g_Wlo[256 * 256];
__device__ int    g_cntI[MAX_NODES];
__device__ int    g_rowptr[MAX_NODES + 1];
__device__ int    g_cursor[MAX_NODES];
__device__ int    g_csrc[MAX_EDGES];
__device__ float  g_cnorm[MAX_EDGES];
__device__ int    g_partial[MAX_SCAN_BLOCKS];

// ========================= helpers =========================
__device__ __forceinline__ void split1(float a, __nv_bfloat16& hi, __nv_bfloat16& lo) {
    hi = __float2bfloat16_rn(a);
    lo = __float2bfloat16_rn(a - __bfloat162float(hi));
}
// split float4 -> packed hi uint2 / lo uint2
__device__ __forceinline__ void split4(float4 a, uint2& hi, uint2& lo) {
    __nv_bfloat16 h0, l0, h1, l1, h2, l2, h3, l3;
    split1(a.x, h0, l0); split1(a.y, h1, l1);
    split1(a.z, h2, l2); split1(a.w, h3, l3);
    __nv_bfloat162 H0(h0, h1), H1(h2, h3), L0(l0, l1), L1(l2, l3);
    hi = make_uint2(*(uint32_t*)&H0, *(uint32_t*)&H1);
    lo = make_uint2(*(uint32_t*)&L0, *(uint32_t*)&L1);
}

#define LDMX4(R, ADDR)                                                          \
    asm volatile("ldmatrix.sync.aligned.m8n8.x4.shared.b16 {%0,%1,%2,%3}, [%4];" \
                 : "=r"((R)[0]), "=r"((R)[1]), "=r"((R)[2]), "=r"((R)[3])        \
                 : "r"(ADDR))

#define MMA16816(D, A, B0, B1)                                                  \
    asm volatile("mma.sync.aligned.m16n8k16.row.col.f32.bf16.bf16.f32 "          \
                 "{%0,%1,%2,%3}, {%4,%5,%6,%7}, {%8,%9}, {%0,%1,%2,%3};"         \
                 : "+f"((D)[0]), "+f"((D)[1]), "+f"((D)[2]), "+f"((D)[3])        \
                 : "r"((A)[0]), "r"((A)[1]), "r"((A)[2]), "r"((A)[3]),           \
                   "r"(B0), "r"(B1))

// ===================== CSR construction =====================
__global__ void k_zero_cnt(int* cnt, int n) {
    int i = blockIdx.x * blockDim.x + threadIdx.x;
    if (i < n) cnt[i] = 0;
}
__global__ void k_count(const int* __restrict__ dst, int* __restrict__ cnt, int nE) {
    int i = blockIdx.x * blockDim.x + threadIdx.x;
    if (i < nE) atomicAdd(&cnt[dst[i]], 1);
}
__global__ void k_scan_p1(const int* __restrict__ cnt, int* __restrict__ partial, int n) {
    __shared__ int s[256];
    int b = blockIdx.x, t = threadIdx.x;
    int base = b * SCAN_CHUNK;
    int i0 = base + t, i1 = base + 256 + t;
    int v = 0;
    if (i0 < n) v += cnt[i0];
    if (i1 < n) v += cnt[i1];
    s[t] = v;
    __syncthreads();
    #pragma unroll
    for (int off = 128; off > 0; off >>= 1) {
        if (t < off) s[t] += s[t + off];
        __syncthreads();
    }
    if (t == 0) partial[b] = s[0];
}
__global__ void k_scan_p2(int* __restrict__ partial, int nb) {
    __shared__ int s[256];
    int t = threadIdx.x;
    int v = (t < nb) ? partial[t] : 0;
    s[t] = v;
    __syncthreads();
    #pragma unroll
    for (int off = 1; off < 256; off <<= 1) {
        int u = (t >= off) ? s[t - off] : 0;
        __syncthreads();
        s[t] += u;
        __syncthreads();
    }
    if (t < nb) partial[t] = s[t] - v;
}
// p3 also computes dinv
__global__ void k_scan_p3(const int* __restrict__ cnt, const int* __restrict__ partial,
                          int* __restrict__ rowptr, int* __restrict__ cursor,
                          float* __restrict__ dinv, int n) {
    __shared__ int s[256];
    int b = blockIdx.x, t = threadIdx.x;
    int base = b * SCAN_CHUNK;
    int i0 = base + 2 * t, i1 = i0 + 1;
    int c0 = (i0 < n) ? cnt[i0] : 0;
    int c1 = (i1 < n) ? cnt[i1] : 0;
    int pairSum = c0 + c1;
    s[t] = pairSum;
    __syncthreads();
    #pragma unroll
    for (int off = 1; off < 256; off <<= 1) {
        int u = (t >= off) ? s[t - off] : 0;
        __syncthreads();
        s[t] += u;
        __syncthreads();
    }
    int pre = s[t] - pairSum + partial[b];
    if (i0 < n) {
        rowptr[i0] = pre; cursor[i0] = pre;
        dinv[i0] = rsqrtf((float)(c0 + 1));
        if (i0 == n - 1) rowptr[n] = pre + c0;
    }
    if (i1 < n) {
        rowptr[i1] = pre + c0; cursor[i1] = pre + c0;
        dinv[i1] = rsqrtf((float)(c1 + 1));
        if (i1 == n - 1) rowptr[n] = pre + c0 + c1;
    }
}
__global__ void k_fill(const int* __restrict__ src, const int* __restrict__ dst,
                       const float* __restrict__ dinv, int* __restrict__ cursor,
                       int* __restrict__ csrc, float* __restrict__ cnorm, int nE) {
    int i = blockIdx.x * blockDim.x + threadIdx.x;
    if (i >= nE) return;
    int s = src[i], d = dst[i];
    int pos = atomicAdd(&cursor[d], 1);
    csrc[pos] = s;
    cnorm[pos] = dinv[s] * dinv[d];
}

// ===================== fp32 -> fp16 conversion =====================
__global__ void k_f2h(const float* __restrict__ X, __half* __restrict__ Xh, long total4) {
    long i = blockIdx.x * (long)blockDim.x + threadIdx.x;
    if (i >= total4) return;
    float4 v = ((const float4*)X)[i];
    __half2 h0 = __floats2half2_rn(v.x, v.y);
    __half2 h1 = __floats2half2_rn(v.z, v.w);
    ((uint2*)Xh)[i] = make_uint2(*(uint32_t*)&h0, *(uint32_t*)&h1);
}

// ===================== CSR gather (fp16 in, bf16 hi/lo out) ==================
__device__ __forceinline__ void acc4h(float4& a, uint2 u, float nm) {
    float2 p0 = __half22float2(*(__half2*)&u.x);
    float2 p1 = __half22float2(*(__half2*)&u.y);
    a.x += nm * p0.x; a.y += nm * p0.y; a.z += nm * p1.x; a.w += nm * p1.y;
}
__device__ __forceinline__ void acc8h(float4& a0, float4& a1, uint4 u, float nm) {
    float2 p0 = __half22float2(*(__half2*)&u.x);
    float2 p1 = __half22float2(*(__half2*)&u.y);
    float2 p2 = __half22float2(*(__half2*)&u.z);
    float2 p3 = __half22float2(*(__half2*)&u.w);
    a0.x += nm * p0.x; a0.y += nm * p0.y; a0.z += nm * p1.x; a0.w += nm * p1.y;
    a1.x += nm * p2.x; a1.y += nm * p2.y; a1.z += nm * p3.x; a1.w += nm * p3.y;
}

// layer 1: self from fp32 X, neighbors fp16; out bf16 hi/lo [n][128]
__global__ __launch_bounds__(256)
void k_gather128h(const float* __restrict__ Xf, const __half* __restrict__ Xh,
                  const int* __restrict__ rowptr, const int* __restrict__ csrc,
                  const float* __restrict__ cnorm, const float* __restrict__ dinv,
                  __nv_bfloat16* __restrict__ AggHi, __nv_bfloat16* __restrict__ AggLo,
                  int n) {
    int node = (blockIdx.x * blockDim.x + threadIdx.x) >> 5;
    if (node >= n) return;
    int lane = threadIdx.x & 31;
    float di = dinv[node];
    float s2 = di * di;
    float4 a = ((const float4*)Xf)[(size_t)node * 32 + lane];
    a.x *= s2; a.y *= s2; a.z *= s2; a.w *= s2;
    const uint2* Xv = (const uint2*)Xh;
    int e = rowptr[node], e1 = rowptr[node + 1];
    for (; e + 4 <= e1; e += 4) {
        int   s0 = csrc[e],  s1 = csrc[e + 1], s2i = csrc[e + 2], s3 = csrc[e + 3];
        float n0 = cnorm[e], n1 = cnorm[e + 1], n2 = cnorm[e + 2], n3 = cnorm[e + 3];
        uint2 u0 = Xv[(size_t)s0 * 32 + lane];
        uint2 u1 = Xv[(size_t)s1 * 32 + lane];
        uint2 u2 = Xv[(size_t)s2i * 32 + lane];
        uint2 u3 = Xv[(size_t)s3 * 32 + lane];
        acc4h(a, u0, n0); acc4h(a, u1, n1); acc4h(a, u2, n2); acc4h(a, u3, n3);
    }
    for (; e < e1; ++e) {
        int s0 = csrc[e]; float n0 = cnorm[e];
        acc4h(a, Xv[(size_t)s0 * 32 + lane], n0);
    }
    uint2 hi, lo;
    split4(a, hi, lo);
    __stcs(&((uint2*)AggHi)[(size_t)node * 32 + lane], hi);
    __stcs(&((uint2*)AggLo)[(size_t)node * 32 + lane], lo);
}

// layer 2: fp16 H (256 cols); out bf16 hi/lo [n][256]
__global__ __launch_bounds__(256)
void k_gather256h(const __half* __restrict__ H,
                  const int* __restrict__ rowptr, const int* __restrict__ csrc,
                  const float* __restrict__ cnorm, const float* __restrict__ dinv,
                  __nv_bfloat16* __restrict__ AggHi, __nv_bfloat16* __restrict__ AggLo,
                  int n) {
    int node = (blockIdx.x * blockDim.x + threadIdx.x) >> 5;
    if (node >= n) return;
    int lane = threadIdx.x & 31;
    float di = dinv[node];
    float s2 = di * di;
    const uint4* Hv = (const uint4*)H;
    float4 a0 = make_float4(0.f, 0.f, 0.f, 0.f);
    float4 a1 = make_float4(0.f, 0.f, 0.f, 0.f);
    acc8h(a0, a1, Hv[(size_t)node * 32 + lane], s2);
    int e = rowptr[node], e1 = rowptr[node + 1];
    for (; e + 4 <= e1; e += 4) {
        int   s0 = csrc[e],  s1 = csrc[e + 1], s2i = csrc[e + 2], s3 = csrc[e + 3];
        float n0 = cnorm[e], n1 = cnorm[e + 1], n2 = cnorm[e + 2], n3 = cnorm[e + 3];
        uint4 u0 = Hv[(size_t)s0 * 32 + lane];
        uint4 u1 = Hv[(size_t)s1 * 32 + lane];
        uint4 u2 = Hv[(size_t)s2i * 32 + lane];
        uint4 u3 = Hv[(size_t)s3 * 32 + lane];
        acc8h(a0, a1, u0, n0); acc8h(a0, a1, u1, n1);
        acc8h(a0, a1, u2, n2); acc8h(a0, a1, u3, n3);
    }
    for (; e < e1; ++e) {
        int s0 = csrc[e]; float n0 = cnorm[e];
        acc8h(a0, a1, Hv[(size_t)s0 * 32 + lane], n0);
    }
    uint2 h0, l0, h1, l1;
    split4(a0, h0, l0);
    split4(a1, h1, l1);
    uint4 hi = make_uint4(h0.x, h0.y, h1.x, h1.y);
    uint4 lo = make_uint4(l0.x, l0.y, l1.x, l1.y);
    __stcs(&((uint4*)AggHi)[(size_t)node * 32 + lane], hi);
    __stcs(&((uint4*)AggLo)[(size_t)node * 32 + lane], lo);
}

// ================= W prep: fp32 [K][256] -> bf16 hi/lo [256][K] =============
__global__ void k_prep_W(const float* __restrict__ W,
                         __nv_bfloat16* __restrict__ Whi,
                         __nv_bfloat16* __restrict__ Wlo, int K) {
    int idx = blockIdx.x * blockDim.x + threadIdx.x;
    if (idx >= K * 256) return;
    int n = idx / K, k = idx % K;
    float v = W[(size_t)k * 256 + n];
    __nv_bfloat16 hi, lo;
    split1(v, hi, lo);
    Whi[idx] = hi;
    Wlo[idx] = lo;
}

// ===================== tensor-core GEMM (M x K) @ (K x 256) =================
// A given pre-split bf16 hi/lo [M][K]. C = relu(A@W + bias) -> fp32 or fp16.
#define BM 128
#define BN 128
#define BK 32
#define LDS_PAD 40

__global__ __launch_bounds__(256, 2)
void k_gemm_mma(const __nv_bfloat16* __restrict__ Ahi,
                const __nv_bfloat16* __restrict__ Alo,
                const __nv_bfloat16* __restrict__ Bhi,
                const __nv_bfloat16* __restrict__ Blo,
                const float* __restrict__ bias,
                float* __restrict__ Cf, __half* __restrict__ Ch,
                int M, int K) {
    __shared__ __align__(16) __nv_bfloat16 sAh[BM * LDS_PAD];
    __shared__ __align__(16) __nv_bfloat16 sAl[BM * LDS_PAD];
    __shared__ __align__(16) __nv_bfloat16 sBh[BN * LDS_PAD];
    __shared__ __align__(16) __nv_bfloat16 sBl[BN * LDS_PAD];

    const int tid = threadIdx.x;
    const int wid = tid >> 5, lane = tid & 31;
    const int warpM = wid & 3;
    const int warpN = wid >> 2;
    const int rowBase = blockIdx.y * BM;
    const int colBase = blockIdx.x * BN;

    float acc[2][8][4];
    #pragma unroll
    for (int i = 0; i < 2; i++)
        #pragma unroll
        for (int j = 0; j < 8; j++)
            #pragma unroll
            for (int q = 0; q < 4; q++) acc[i][j][q] = 0.f;

    const int aRow = warpM * 32 + (lane & 15);
    const int aK   = (lane >> 4) * 8;
    const int bRowBase = warpN * 64 + (lane & 7) + ((lane >> 4) << 3);
    const int bK   = ((lane >> 3) & 1) * 8;

    uint32_t sAh_b = (uint32_t)__cvta_generic_to_shared(sAh);
    uint32_t sAl_b = (uint32_t)__cvta_generic_to_shared(sAl);
    uint32_t sBh_b = (uint32_t)__cvta_generic_to_shared(sBh);
    uint32_t sBl_b = (uint32_t)__cvta_generic_to_shared(sBl);

    const uint4 zero4 = make_uint4(0u, 0u, 0u, 0u);

    for (int k0 = 0; k0 < K; k0 += BK) {
        // ---- A tile: 128 rows x 32 cols bf16 hi/lo (pure copies) ----
        {
            #pragma unroll
            for (int it = 0; it < 2; ++it) {
                int i = tid + it * 256;
                int r  = i >> 2;           // 0..127
                int c8 = (i & 3) * 8;      // 0,8,16,24
                int gr = rowBase + r;
                int off = r * LDS_PAD + c8;
                size_t g = (size_t)gr * K + k0 + c8;
                uint4 vh = zero4, vl = zero4;
                if (gr < M) {
                    vh = *(const uint4*)(Ahi + g);
                    vl = *(const uint4*)(Alo + g);
                }
                *(uint4*)&sAh[off] = vh;
                *(uint4*)&sAl[off] = vl;
            }
        }
        // ---- B tile ----
        {
            #pragma unroll
            for (int it = 0; it < 2; ++it) {
                int i = tid + it * 256;
                int nn = i >> 2;
                int kq = (i & 3) * 8;
                int off = nn * LDS_PAD + kq;
                const size_t g = (size_t)(colBase + nn) * K + k0 + kq;
                *(uint4*)&sBh[off] = *(const uint4*)(Bhi + g);
                *(uint4*)&sBl[off] = *(const uint4*)(Blo + g);
            }
        }
        __syncthreads();

        #pragma unroll
        for (int kk = 0; kk < BK; kk += 16) {
            uint32_t aH[2][4], aL[2][4];
            #pragma unroll
            for (int mi = 0; mi < 2; ++mi) {
                uint32_t o = (uint32_t)((aRow + mi * 16) * LDS_PAD + kk + aK) * 2;
                LDMX4(aH[mi], sAh_b + o);
                LDMX4(aL[mi], sAl_b + o);
            }
            #pragma unroll
            for (int nj = 0; nj < 4; ++nj) {
                uint32_t bH[4], bL[4];
                uint32_t o = (uint32_t)((bRowBase + nj * 16) * LDS_PAD + kk + bK) * 2;
                LDMX4(bH, sBh_b + o);
                LDMX4(bL, sBl_b + o);
                #pragma unroll
                for (int mi = 0; mi < 2; ++mi) {
                    MMA16816(acc[mi][nj * 2 + 0], aH[mi], bH[0], bH[1]);
                    MMA16816(acc[mi][nj * 2 + 1], aH[mi], bH[2], bH[3]);
                    MMA16816(acc[mi][nj * 2 + 0], aH[mi], bL[0], bL[1]);
                    MMA16816(acc[mi][nj * 2 + 1], aH[mi], bL[2], bL[3]);
                    MMA16816(acc[mi][nj * 2 + 0], aL[mi], bH[0], bH[1]);
                    MMA16816(acc[mi][nj * 2 + 1], aL[mi], bH[2], bH[3]);
                }
            }
        }
        __syncthreads();
    }

    const int erow = rowBase + warpM * 32 + (lane >> 2);
    const int ecol = colBase + warpN * 64 + (lane & 3) * 2;
    #pragma unroll
    for (int mi = 0; mi < 2; ++mi) {
        int r0 = erow + mi * 16;
        #pragma unroll
        for (int nj = 0; nj < 8; ++nj) {
            int c = ecol + nj * 8;
            float b0 = bias[c], b1 = bias[c + 1];
            float v00 = fmaxf(acc[mi][nj][0] + b0, 0.f);
            float v01 = fmaxf(acc[mi][nj][1] + b1, 0.f);
            float v10 = fmaxf(acc[mi][nj][2] + b0, 0.f);
            float v11 = fmaxf(acc[mi][nj][3] + b1, 0.f);
            if (Cf) {
                if (r0 < M)     *(float2*)(Cf + (size_t)r0 * 256 + c)       = make_float2(v00, v01);
                if (r0 + 8 < M) *(float2*)(Cf + (size_t)(r0 + 8) * 256 + c) = make_float2(v10, v11);
            } else {
                if (r0 < M)     *(__half2*)(Ch + (size_t)r0 * 256 + c)       = __floats2half2_rn(v00, v01);
                if (r0 + 8 < M) *(__half2*)(Ch + (size_t)(r0 + 8) * 256 + c) = __floats2half2_rn(v10, v11);
            }
        }
    }
}

// ============ pooling: sorted-segment mean, one warp per graph =============
__global__ __launch_bounds__(256)
void k_pool_seg(const float* __restrict__ H, const int* __restrict__ batch,
                float* __restrict__ pool, int n) {
    int g = (blockIdx.x * blockDim.x + threadIdx.x) >> 5;
    if (g >= NGRAPH) return;
    int lane = threadIdx.x & 31;
    int lo = 0, hi = n;
    while (lo < hi) { int mid = (lo + hi) >> 1; if (batch[mid] < g) lo = mid + 1; else hi = mid; }
    int start = lo;
    hi = n;
    while (lo < hi) { int mid = (lo + hi) >> 1; if (batch[mid] < g + 1) lo = mid + 1; else hi = mid; }
    int end = lo;

    float4 a0 = make_float4(0.f, 0.f, 0.f, 0.f);
    float4 a1 = make_float4(0.f, 0.f, 0.f, 0.f);
    const float4* Hv = (const float4*)H;
    for (int i = start; i < end; ++i) {
        size_t b = (size_t)i * 64 + lane;
        float4 v0 = Hv[b], v1 = Hv[b + 32];
        a0.x += v0.x; a0.y += v0.y; a0.z += v0.z; a0.w += v0.w;
        a1.x += v1.x; a1.y += v1.y; a1.z += v1.z; a1.w += v1.w;
    }
    float inv = (end > start) ? 1.0f / (float)(end - start) : 0.f;
    a0.x *= inv; a0.y *= inv; a0.z *= inv; a0.w *= inv;
    a1.x *= inv; a1.y *= inv; a1.z *= inv; a1.w *= inv;
    size_t pb = (size_t)g * 64 + lane;
    ((float4*)pool)[pb] = a0;
    ((float4*)pool)[pb + 32] = a1;
}

// ================================ MLP head =================================
__global__ void k_mlp(const float* __restrict__ pool,
                      const float* __restrict__ Wf1, const float* __restrict__ bf1,
                      const float* __restrict__ Wf2, const float* __restrict__ bf2,
                      float* __restrict__ out) {
    int g = blockIdx.x;
    __shared__ float p[HID];
    __shared__ float red[128];
    int t = threadIdx.x;
    p[t]       = pool[g * HID + t];
    p[t + 128] = pool[g * HID + 128 + t];
    __syncthreads();
    float acc = bf1[t];
    #pragma unroll 8
    for (int k = 0; k < HID; k++) acc += p[k] * Wf1[k * 128 + t];
    red[t] = fmaxf(acc, 0.f) * Wf2[t];
    __syncthreads();
    for (int s = 64; s > 0; s >>= 1) {
        if (t < s) red[t] += red[t + s];
        __syncthreads();
    }
    if (t == 0) out[g] = red[0] + bf2[0];
}

// ---------------------------------------------------------------------------
extern "C" void kernel_launch(void* const* d_in, const int* in_sizes, int n_in,
                              void* d_out, int out_size) {
    const float* x   = (const float*)d_in[0];
    const int*   ei  = (const int*)d_in[1];
    const int*   bat = (const int*)d_in[2];
    const float* W1  = (const float*)d_in[3];
    const float* b1  = (const float*)d_in[4];
    const float* W2  = (const float*)d_in[5];
    const float* b2  = (const float*)d_in[6];
    const float* Wf1 = (const float*)d_in[7];
    const float* bf1 = (const float*)d_in[8];
    const float* Wf2 = (const float*)d_in[9];
    const float* bf2 = (const float*)d_in[10];
    float* out = (float*)d_out;

    int n  = in_sizes[0] / 128;
    int nE = in_sizes[1] / 2;
    const int* src = ei;
    const int* dst = ei + nE;

    float *bufB, *dinv, *pool;
    __half *h1h, *xh;
    __nv_bfloat16 *Whi, *Wlo, *aggHi, *aggLo;
    int *cntI, *rowptr, *cursor, *csrc, *partial;
    float *cnorm;
    cudaGetSymbolAddress((void**)&aggHi, g_aggHi);
    cudaGetSymbolAddress((void**)&aggLo, g_aggLo);
    cudaGetSymbolAddress((void**)&bufB, g_bufB);
    cudaGetSymbolAddress((void**)&h1h,  g_h1h);
    cudaGetSymbolAddress((void**)&xh,   g_xh);
    cudaGetSymbolAddress((void**)&dinv, g_dinv);
    cudaGetSymbolAddress((void**)&pool, g_pool);
    cudaGetSymbolAddress((void**)&Whi,  g_Whi);
    cudaGetSymbolAddress((void**)&Wlo,  g_Wlo);
    cudaGetSymbolAddress((void**)&cntI, g_cntI);
    cudaGetSymbolAddress((void**)&rowptr, g_rowptr);
    cudaGetSymbolAddress((void**)&cursor, g_cursor);
    cudaGetSymbolAddress((void**)&csrc, g_csrc);
    cudaGetSymbolAddress((void**)&cnorm, g_cnorm);
    cudaGetSymbolAddress((void**)&partial, g_partial);

    // --- CSR build + x->fp16 ---
    int nb = (n + SCAN_CHUNK - 1) / SCAN_CHUNK;
    k_zero_cnt<<<(n + 255) / 256, 256>>>(cntI, n);
    k_count<<<(nE + 255) / 256, 256>>>(dst, cntI, nE);
    k_scan_p1<<<nb, 256>>>(cntI, partial, n);
    k_scan_p2<<<1, 256>>>(partial, nb);
    k_scan_p3<<<nb, 256>>>(cntI, partial, rowptr, cursor, dinv, n);
    k_fill<<<(nE + 255) / 256, 256>>>(src, dst, dinv, cursor, csrc, cnorm, nE);
    {
        long t4 = (long)n * 32;
        k_f2h<<<(unsigned)((t4 + 255) / 256), 256>>>(x, xh, t4);
    }

    dim3 gemmGrid(2, (n + BM - 1) / BM);
    unsigned gatherBlocks = (unsigned)(((long)n * 32 + 255) / 256);

    // --- layer 1 ---
    k_gather128h<<<gatherBlocks, 256>>>(x, xh, rowptr, csrc, cnorm, dinv, aggHi, aggLo, n);
    k_prep_W<<<(128 * 256 + 255) / 256, 256>>>(W1, Whi, Wlo, 128);
    k_gemm_mma<<<gemmGrid, 256>>>(aggHi, aggLo, Whi, Wlo, b1, nullptr, h1h, n, 128);

    // --- layer 2 ---
    k_gather256h<<<gatherBlocks, 256>>>(h1h, rowptr, csrc, cnorm, dinv, aggHi, aggLo, n);
    k_prep_W<<<(256 * 256 + 255) / 256, 256>>>(W2, Whi, Wlo, 256);
    k_gemm_mma<<<gemmGrid, 256>>>(aggHi, aggLo, Whi, Wlo, b2, bufB, nullptr, n, 256);

    // --- pooling + MLP head ---
    {
        unsigned poolBlocks = (unsigned)(((long)NGRAPH * 32 + 255) / 256);
        k_pool_seg<<<poolBlocks, 256>>>(bufB, bat, pool, n);
    }
    k_mlp<<<NGRAPH, 128>>>(pool, Wf1, bf1, Wf2, bf2, out);
}

// round 9
// speedup vs baseline: 1.2812x; 1.1585x over previous
#include <cuda_runtime.h>
#include <cuda_fp16.h>
#include <cstdint>

// ---------------------------------------------------------------------------
// GCN: h1 = relu((ÂX)W1 + b1); h2 = relu((Âh1)W2 + b2); mean pool; MLP head.
// CSR gather (fp16 operands, fp32 accum) -> fp16 agg; GEMMs: fp16 A (single)
// x fp16 W (hi/lo split) HMMA with fp32 accum; sorted-segment pooling.
// ---------------------------------------------------------------------------

#define MAX_NODES 100000
#define MAX_EDGES 1700000
#define HID 256
#define NGRAPH 2048
#define SCAN_CHUNK 512
#define MAX_SCAN_BLOCKS ((MAX_NODES + SCAN_CHUNK - 1) / SCAN_CHUNK)

__device__ __half g_aggH[(size_t)MAX_NODES * HID];   // agg (fp16, GEMM A)
__device__ __half g_h1h[(size_t)MAX_NODES * HID];    // h1 (fp16)
__device__ __half g_h2h[(size_t)MAX_NODES * HID];    // h2 (fp16)
__device__ __half g_xh[(size_t)MAX_NODES * 128];     // x (fp16)
__device__ float  g_dinv[MAX_NODES];
__device__ float  g_pool[NGRAPH * HID];
__device__ __half g_Whi[256 * 256];                  // W^T hi [N][K]
__device__ __half g_Wlo[256 * 256];                  // W^T lo [N][K]
__device__ int    g_cntI[MAX_NODES];
__device__ int    g_rowptr[MAX_NODES + 1];
__device__ int    g_cursor[MAX_NODES];
__device__ int    g_csrc[MAX_EDGES];
__device__ float  g_cnorm[MAX_EDGES];
__device__ int    g_partial[MAX_SCAN_BLOCKS];

// ========================= helpers =========================
#define LDMX4(R, ADDR)                                                          \
    asm volatile("ldmatrix.sync.aligned.m8n8.x4.shared.b16 {%0,%1,%2,%3}, [%4];" \
                 : "=r"((R)[0]), "=r"((R)[1]), "=r"((R)[2]), "=r"((R)[3])        \
                 : "r"(ADDR))

#define MMAF16(D, A, B0, B1)                                                    \
    asm volatile("mma.sync.aligned.m16n8k16.row.col.f32.f16.f16.f32 "            \
                 "{%0,%1,%2,%3}, {%4,%5,%6,%7}, {%8,%9}, {%0,%1,%2,%3};"         \
                 : "+f"((D)[0]), "+f"((D)[1]), "+f"((D)[2]), "+f"((D)[3])        \
                 : "r"((A)[0]), "r"((A)[1]), "r"((A)[2]), "r"((A)[3]),           \
                   "r"(B0), "r"(B1))

// ===================== CSR construction =====================
__global__ void k_zero_cnt(int* cnt, int n) {
    int i = blockIdx.x * blockDim.x + threadIdx.x;
    if (i < n) cnt[i] = 0;
}
__global__ void k_count(const int* __restrict__ dst, int* __restrict__ cnt, int nE) {
    int i = blockIdx.x * blockDim.x + threadIdx.x;
    if (i < nE) atomicAdd(&cnt[dst[i]], 1);
}
__global__ void k_scan_p1(const int* __restrict__ cnt, int* __restrict__ partial, int n) {
    __shared__ int s[256];
    int b = blockIdx.x, t = threadIdx.x;
    int base = b * SCAN_CHUNK;
    int i0 = base + t, i1 = base + 256 + t;
    int v = 0;
    if (i0 < n) v += cnt[i0];
    if (i1 < n) v += cnt[i1];
    s[t] = v;
    __syncthreads();
    #pragma unroll
    for (int off = 128; off > 0; off >>= 1) {
        if (t < off) s[t] += s[t + off];
        __syncthreads();
    }
    if (t == 0) partial[b] = s[0];
}
__global__ void k_scan_p2(int* __restrict__ partial, int nb) {
    __shared__ int s[256];
    int t = threadIdx.x;
    int v = (t < nb) ? partial[t] : 0;
    s[t] = v;
    __syncthreads();
    #pragma unroll
    for (int off = 1; off < 256; off <<= 1) {
        int u = (t >= off) ? s[t - off] : 0;
        __syncthreads();
        s[t] += u;
        __syncthreads();
    }
    if (t < nb) partial[t] = s[t] - v;
}
__global__ void k_scan_p3(const int* __restrict__ cnt, const int* __restrict__ partial,
                          int* __restrict__ rowptr, int* __restrict__ cursor,
                          float* __restrict__ dinv, int n) {
    __shared__ int s[256];
    int b = blockIdx.x, t = threadIdx.x;
    int base = b * SCAN_CHUNK;
    int i0 = base + 2 * t, i1 = i0 + 1;
    int c0 = (i0 < n) ? cnt[i0] : 0;
    int c1 = (i1 < n) ? cnt[i1] : 0;
    int pairSum = c0 + c1;
    s[t] = pairSum;
    __syncthreads();
    #pragma unroll
    for (int off = 1; off < 256; off <<= 1) {
        int u = (t >= off) ? s[t - off] : 0;
        __syncthreads();
        s[t] += u;
        __syncthreads();
    }
    int pre = s[t] - pairSum + partial[b];
    if (i0 < n) {
        rowptr[i0] = pre; cursor[i0] = pre;
        dinv[i0] = rsqrtf((float)(c0 + 1));
        if (i0 == n - 1) rowptr[n] = pre + c0;
    }
    if (i1 < n) {
        rowptr[i1] = pre + c0; cursor[i1] = pre + c0;
        dinv[i1] = rsqrtf((float)(c1 + 1));
        if (i1 == n - 1) rowptr[n] = pre + c0 + c1;
    }
}
__global__ void k_fill(const int* __restrict__ src, const int* __restrict__ dst,
                       const float* __restrict__ dinv, int* __restrict__ cursor,
                       int* __restrict__ csrc, float* __restrict__ cnorm, int nE) {
    int i = blockIdx.x * blockDim.x + threadIdx.x;
    if (i >= nE) return;
    int s = src[i], d = dst[i];
    int pos = atomicAdd(&cursor[d], 1);
    csrc[pos] = s;
    cnorm[pos] = dinv[s] * dinv[d];
}

// ===================== fp32 -> fp16 conversion =====================
__global__ void k_f2h(const float* __restrict__ X, __half* __restrict__ Xh, long total4) {
    long i = blockIdx.x * (long)blockDim.x + threadIdx.x;
    if (i >= total4) return;
    float4 v = ((const float4*)X)[i];
    __half2 h0 = __floats2half2_rn(v.x, v.y);
    __half2 h1 = __floats2half2_rn(v.z, v.w);
    ((uint2*)Xh)[i] = make_uint2(*(uint32_t*)&h0, *(uint32_t*)&h1);
}

// ===================== CSR gather (fp16 in, fp16 out) ==================
__device__ __forceinline__ void acc4h(float4& a, uint2 u, float nm) {
    float2 p0 = __half22float2(*(__half2*)&u.x);
    float2 p1 = __half22float2(*(__half2*)&u.y);
    a.x += nm * p0.x; a.y += nm * p0.y; a.z += nm * p1.x; a.w += nm * p1.y;
}
__device__ __forceinline__ void acc8h(float4& a0, float4& a1, uint4 u, float nm) {
    float2 p0 = __half22float2(*(__half2*)&u.x);
    float2 p1 = __half22float2(*(__half2*)&u.y);
    float2 p2 = __half22float2(*(__half2*)&u.z);
    float2 p3 = __half22float2(*(__half2*)&u.w);
    a0.x += nm * p0.x; a0.y += nm * p0.y; a0.z += nm * p1.x; a0.w += nm * p1.y;
    a1.x += nm * p2.x; a1.y += nm * p2.y; a1.z += nm * p3.x; a1.w += nm * p3.y;
}
__device__ __forceinline__ uint2 pack4h(float4 a) {
    __half2 h0 = __floats2half2_rn(a.x, a.y);
    __half2 h1 = __floats2half2_rn(a.z, a.w);
    return make_uint2(*(uint32_t*)&h0, *(uint32_t*)&h1);
}

// layer 1: 128 cols; cols 4*lane..4*lane+3 per lane
__global__ __launch_bounds__(256)
void k_gather128h(const __half* __restrict__ Xh,
                  const int* __restrict__ rowptr, const int* __restrict__ csrc,
                  const float* __restrict__ cnorm, const float* __restrict__ dinv,
                  __half* __restrict__ Agg, int n) {
    int node = (blockIdx.x * blockDim.x + threadIdx.x) >> 5;
    if (node >= n) return;
    int lane = threadIdx.x & 31;
    float di = dinv[node];
    float s2 = di * di;
    const uint2* Xv = (const uint2*)Xh;
    float4 a = make_float4(0.f, 0.f, 0.f, 0.f);
    acc4h(a, Xv[(size_t)node * 32 + lane], s2);   // self-loop
    int e = rowptr[node], e1 = rowptr[node + 1];
    for (; e + 4 <= e1; e += 4) {
        int   s0 = csrc[e],  s1 = csrc[e + 1], s2i = csrc[e + 2], s3 = csrc[e + 3];
        float n0 = cnorm[e], n1 = cnorm[e + 1], n2 = cnorm[e + 2], n3 = cnorm[e + 3];
        uint2 u0 = Xv[(size_t)s0 * 32 + lane];
        uint2 u1 = Xv[(size_t)s1 * 32 + lane];
        uint2 u2 = Xv[(size_t)s2i * 32 + lane];
        uint2 u3 = Xv[(size_t)s3 * 32 + lane];
        acc4h(a, u0, n0); acc4h(a, u1, n1); acc4h(a, u2, n2); acc4h(a, u3, n3);
    }
    for (; e < e1; ++e) {
        int s0 = csrc[e]; float n0 = cnorm[e];
        acc4h(a, Xv[(size_t)s0 * 32 + lane], n0);
    }
    __stcs(&((uint2*)Agg)[(size_t)node * 32 + lane], pack4h(a));
}

// layer 2: 256 cols; cols 8*lane..8*lane+7 per lane
__global__ __launch_bounds__(256)
void k_gather256h(const __half* __restrict__ H,
                  const int* __restrict__ rowptr, const int* __restrict__ csrc,
                  const float* __restrict__ cnorm, const float* __restrict__ dinv,
                  __half* __restrict__ Agg, int n) {
    int node = (blockIdx.x * blockDim.x + threadIdx.x) >> 5;
    if (node >= n) return;
    int lane = threadIdx.x & 31;
    float di = dinv[node];
    float s2 = di * di;
    const uint4* Hv = (const uint4*)H;
    float4 a0 = make_float4(0.f, 0.f, 0.f, 0.f);
    float4 a1 = make_float4(0.f, 0.f, 0.f, 0.f);
    acc8h(a0, a1, Hv[(size_t)node * 32 + lane], s2);
    int e = rowptr[node], e1 = rowptr[node + 1];
    for (; e + 4 <= e1; e += 4) {
        int   s0 = csrc[e],  s1 = csrc[e + 1], s2i = csrc[e + 2], s3 = csrc[e + 3];
        float n0 = cnorm[e], n1 = cnorm[e + 1], n2 = cnorm[e + 2], n3 = cnorm[e + 3];
        uint4 u0 = Hv[(size_t)s0 * 32 + lane];
        uint4 u1 = Hv[(size_t)s1 * 32 + lane];
        uint4 u2 = Hv[(size_t)s2i * 32 + lane];
        uint4 u3 = Hv[(size_t)s3 * 32 + lane];
        acc8h(a0, a1, u0, n0); acc8h(a0, a1, u1, n1);
        acc8h(a0, a1, u2, n2); acc8h(a0, a1, u3, n3);
    }
    for (; e < e1; ++e) {
        int s0 = csrc[e]; float n0 = cnorm[e];
        acc8h(a0, a1, Hv[(size_t)s0 * 32 + lane], n0);
    }
    uint2 p0 = pack4h(a0), p1 = pack4h(a1);
    __stcs(&((uint4*)Agg)[(size_t)node * 32 + lane], make_uint4(p0.x, p0.y, p1.x, p1.y));
}

// ================= W prep: fp32 [K][256] -> fp16 hi/lo [256][K] =============
__global__ void k_prep_W(const float* __restrict__ W,
                         __half* __restrict__ Whi, __half* __restrict__ Wlo, int K) {
    int idx = blockIdx.x * blockDim.x + threadIdx.x;
    if (idx >= K * 256) return;
    int n = idx / K, k = idx % K;
    float v = W[(size_t)k * 256 + n];
    __half hi = __float2half_rn(v);
    __half lo = __float2half_rn(v - __half2float(hi));
    Whi[idx] = hi;
    Wlo[idx] = lo;
}

// ===================== tensor-core GEMM (M x K) @ (K x 256) =================
// A fp16 [M][K]; W fp16 hi/lo pre-transposed [256][K]. C = relu(A@W + bias) fp16.
#define BM 128
#define BN 128
#define BK 32
#define LDS_PAD 40

__global__ __launch_bounds__(256, 2)
void k_gemm_mma(const __half* __restrict__ A,
                const __half* __restrict__ Bhi, const __half* __restrict__ Blo,
                const float* __restrict__ bias, __half* __restrict__ C,
                int M, int K) {
    __shared__ __align__(16) __half sA[BM * LDS_PAD];
    __shared__ __align__(16) __half sBh[BN * LDS_PAD];
    __shared__ __align__(16) __half sBl[BN * LDS_PAD];

    const int tid = threadIdx.x;
    const int wid = tid >> 5, lane = tid & 31;
    const int warpM = wid & 3;
    const int warpN = wid >> 2;
    const int rowBase = blockIdx.y * BM;
    const int colBase = blockIdx.x * BN;

    float acc[2][8][4];
    #pragma unroll
    for (int i = 0; i < 2; i++)
        #pragma unroll
        for (int j = 0; j < 8; j++)
            #pragma unroll
            for (int q = 0; q < 4; q++) acc[i][j][q] = 0.f;

    const int aRow = warpM * 32 + (lane & 15);
    const int aK   = (lane >> 4) * 8;
    const int bRowBase = warpN * 64 + (lane & 7) + ((lane >> 4) << 3);
    const int bK   = ((lane >> 3) & 1) * 8;

    uint32_t sA_b  = (uint32_t)__cvta_generic_to_shared(sA);
    uint32_t sBh_b = (uint32_t)__cvta_generic_to_shared(sBh);
    uint32_t sBl_b = (uint32_t)__cvta_generic_to_shared(sBl);

    const uint4 zero4 = make_uint4(0u, 0u, 0u, 0u);

    for (int k0 = 0; k0 < K; k0 += BK) {
        // ---- A tile: 128 rows x 32 cols fp16 (pure copies) ----
        {
            #pragma unroll
            for (int it = 0; it < 2; ++it) {
                int i = tid + it * 256;
                int r  = i >> 2;           // 0..127
                int c8 = (i & 3) * 8;      // 0,8,16,24 (halves)
                int gr = rowBase + r;
                uint4 v = zero4;
                if (gr < M) v = *(const uint4*)(A + (size_t)gr * K + k0 + c8);
                *(uint4*)&sA[r * LDS_PAD + c8] = v;
            }
        }
        // ---- B tile hi/lo ----
        {
            #pragma unroll
            for (int it = 0; it < 2; ++it) {
                int i = tid + it * 256;
                int nn = i >> 2;
                int kq = (i & 3) * 8;
                int off = nn * LDS_PAD + kq;
                const size_t g = (size_t)(colBase + nn) * K + k0 + kq;
                *(uint4*)&sBh[off] = *(const uint4*)(Bhi + g);
                *(uint4*)&sBl[off] = *(const uint4*)(Blo + g);
            }
        }
        __syncthreads();

        #pragma unroll
        for (int kk = 0; kk < BK; kk += 16) {
            uint32_t aR[2][4];
            #pragma unroll
            for (int mi = 0; mi < 2; ++mi) {
                uint32_t o = (uint32_t)((aRow + mi * 16) * LDS_PAD + kk + aK) * 2;
                LDMX4(aR[mi], sA_b + o);
            }
            #pragma unroll
            for (int nj = 0; nj < 4; ++nj) {
                uint32_t bH[4], bL[4];
                uint32_t o = (uint32_t)((bRowBase + nj * 16) * LDS_PAD + kk + bK) * 2;
                LDMX4(bH, sBh_b + o);
                LDMX4(bL, sBl_b + o);
                #pragma unroll
                for (int mi = 0; mi < 2; ++mi) {
                    MMAF16(acc[mi][nj * 2 + 0], aR[mi], bH[0], bH[1]);
                    MMAF16(acc[mi][nj * 2 + 1], aR[mi], bH[2], bH[3]);
                    MMAF16(acc[mi][nj * 2 + 0], aR[mi], bL[0], bL[1]);
                    MMAF16(acc[mi][nj * 2 + 1], aR[mi], bL[2], bL[3]);
                }
            }
        }
        __syncthreads();
    }

    const int erow = rowBase + warpM * 32 + (lane >> 2);
    const int ecol = colBase + warpN * 64 + (lane & 3) * 2;
    #pragma unroll
    for (int mi = 0; mi < 2; ++mi) {
        int r0 = erow + mi * 16;
        #pragma unroll
        for (int nj = 0; nj < 8; ++nj) {
            int c = ecol + nj * 8;
            float b0 = bias[c], b1 = bias[c + 1];
            float v00 = fmaxf(acc[mi][nj][0] + b0, 0.f);
            float v01 = fmaxf(acc[mi][nj][1] + b1, 0.f);
            float v10 = fmaxf(acc[mi][nj][2] + b0, 0.f);
            float v11 = fmaxf(acc[mi][nj][3] + b1, 0.f);
            if (r0 < M)     *(__half2*)(C + (size_t)r0 * 256 + c)       = __floats2half2_rn(v00, v01);
            if (r0 + 8 < M) *(__half2*)(C + (size_t)(r0 + 8) * 256 + c) = __floats2half2_rn(v10, v11);
        }
    }
}

// ============ pooling: sorted-segment mean (fp16 in, fp32 out) =============
__global__ __launch_bounds__(256)
void k_pool_seg(const __half* __restrict__ H, const int* __restrict__ batch,
                float* __restrict__ pool, int n) {
    int g = (blockIdx.x * blockDim.x + threadIdx.x) >> 5;
    if (g >= NGRAPH) return;
    int lane = threadIdx.x & 31;
    int lo = 0, hi = n;
    while (lo < hi) { int mid = (lo + hi) >> 1; if (batch[mid] < g) lo = mid + 1; else hi = mid; }
    int start = lo;
    hi = n;
    while (lo < hi) { int mid = (lo + hi) >> 1; if (batch[mid] < g + 1) lo = mid + 1; else hi = mid; }
    int end = lo;

    float4 a0 = make_float4(0.f, 0.f, 0.f, 0.f);
    float4 a1 = make_float4(0.f, 0.f, 0.f, 0.f);
    const uint4* Hv = (const uint4*)H;
    for (int i = start; i < end; ++i) {
        acc8h(a0, a1, Hv[(size_t)i * 32 + lane], 1.0f);
    }
    float inv = (end > start) ? 1.0f / (float)(end - start) : 0.f;
    a0.x *= inv; a0.y *= inv; a0.z *= inv; a0.w *= inv;
    a1.x *= inv; a1.y *= inv; a1.z *= inv; a1.w *= inv;
    // lane covers cols 8*lane..8*lane+7 -> float4 indices 2*lane, 2*lane+1
    ((float4*)pool)[(size_t)g * 64 + 2 * lane]     = a0;
    ((float4*)pool)[(size_t)g * 64 + 2 * lane + 1] = a1;
}

// ================================ MLP head =================================
__global__ void k_mlp(const float* __restrict__ pool,
                      const float* __restrict__ Wf1, const float* __restrict__ bf1,
                      const float* __restrict__ Wf2, const float* __restrict__ bf2,
                      float* __restrict__ out) {
    int g = blockIdx.x;
    __shared__ float p[HID];
    __shared__ float red[128];
    int t = threadIdx.x;
    p[t]       = pool[g * HID + t];
    p[t + 128] = pool[g * HID + 128 + t];
    __syncthreads();
    float acc = bf1[t];
    #pragma unroll 8
    for (int k = 0; k < HID; k++) acc += p[k] * Wf1[k * 128 + t];
    red[t] = fmaxf(acc, 0.f) * Wf2[t];
    __syncthreads();
    for (int s = 64; s > 0; s >>= 1) {
        if (t < s) red[t] += red[t + s];
        __syncthreads();
    }
    if (t == 0) out[g] = red[0] + bf2[0];
}

// ---------------------------------------------------------------------------
extern "C" void kernel_launch(void* const* d_in, const int* in_sizes, int n_in,
                              void* d_out, int out_size) {
    const float* x   = (const float*)d_in[0];
    const int*   ei  = (const int*)d_in[1];
    const int*   bat = (const int*)d_in[2];
    const float* W1  = (const float*)d_in[3];
    const float* b1  = (const float*)d_in[4];
    const float* W2  = (const float*)d_in[5];
    const float* b2  = (const float*)d_in[6];
    const float* Wf1 = (const float*)d_in[7];
    const float* bf1 = (const float*)d_in[8];
    const float* Wf2 = (const float*)d_in[9];
    const float* bf2 = (const float*)d_in[10];
    float* out = (float*)d_out;

    int n  = in_sizes[0] / 128;
    int nE = in_sizes[1] / 2;
    const int* src = ei;
    const int* dst = ei + nE;

    float *dinv, *pool, *cnorm;
    __half *aggH, *h1h, *h2h, *xh, *Whi, *Wlo;
    int *cntI, *rowptr, *cursor, *csrc, *partial;
    cudaGetSymbolAddress((void**)&aggH, g_aggH);
    cudaGetSymbolAddress((void**)&h1h,  g_h1h);
    cudaGetSymbolAddress((void**)&h2h,  g_h2h);
    cudaGetSymbolAddress((void**)&xh,   g_xh);
    cudaGetSymbolAddress((void**)&dinv, g_dinv);
    cudaGetSymbolAddress((void**)&pool, g_pool);
    cudaGetSymbolAddress((void**)&Whi,  g_Whi);
    cudaGetSymbolAddress((void**)&Wlo,  g_Wlo);
    cudaGetSymbolAddress((void**)&cntI, g_cntI);
    cudaGetSymbolAddress((void**)&rowptr, g_rowptr);
    cudaGetSymbolAddress((void**)&cursor, g_cursor);
    cudaGetSymbolAddress((void**)&csrc, g_csrc);
    cudaGetSymbolAddress((void**)&cnorm, g_cnorm);
    cudaGetSymbolAddress((void**)&partial, g_partial);

    // --- CSR build + x->fp16 ---
    int nb = (n + SCAN_CHUNK - 1) / SCAN_CHUNK;
    k_zero_cnt<<<(n + 255) / 256, 256>>>(cntI, n);
    k_count<<<(nE + 255) / 256, 256>>>(dst, cntI, nE);
    k_scan_p1<<<nb, 256>>>(cntI, partial, n);
    k_scan_p2<<<1, 256>>>(partial, nb);
    k_scan_p3<<<nb, 256>>>(cntI, partial, rowptr, cursor, dinv, n);
    k_fill<<<(nE + 255) / 256, 256>>>(src, dst, dinv, cursor, csrc, cnorm, nE);
    {
        long t4 = (long)n * 32;
        k_f2h<<<(unsigned)((t4 + 255) / 256), 256>>>(x, xh, t4);
    }

    dim3 gemmGrid(2, (n + BM - 1) / BM);
    unsigned gatherBlocks = (unsigned)(((long)n * 32 + 255) / 256);

    // --- layer 1 ---
    k_gather128h<<<gatherBlocks, 256>>>(xh, rowptr, csrc, cnorm, dinv, aggH, n);
    k_prep_W<<<(128 * 256 + 255) / 256, 256>>>(W1, Whi, Wlo, 128);
    k_gemm_mma<<<gemmGrid, 256>>>(aggH, Whi, Wlo, b1, h1h, n, 128);

    // --- layer 2 ---
    k_gather256h<<<gatherBlocks, 256>>>(h1h, rowptr, csrc, cnorm, dinv, aggH, n);
    k_prep_W<<<(256 * 256 + 255) / 256, 256>>>(W2, Whi, Wlo, 256);
    k_gemm_mma<<<gemmGrid, 256>>>(aggH, Whi, Wlo, b2, h2h, n, 256);

    // --- pooling + MLP head ---
    {
        unsigned poolBlocks = (unsigned)(((long)NGRAPH * 32 + 255) / 256);
        k_pool_seg<<<poolBlocks, 256>>>(h2h, bat, pool, n);
    }
    k_mlp<<<NGRAPH, 128>>>(pool, Wf1, bf1, Wf2, bf2, out);
}

// round 10
// speedup vs baseline: 1.2955x; 1.0112x over previous
#include <cuda_runtime.h>
#include <cuda_fp16.h>
#include <cstdint>

// ---------------------------------------------------------------------------
// GCN: h1 = relu((ÂX)W1 + b1); h2 = relu((Âh1)W2 + b2); mean pool; MLP head.
// CSR gather (fp16 operands, fp32 accum, packed edge records) -> fp16 agg;
// pure fp16 HMMA GEMMs (fp32 accum); sorted-segment pooling.
// ---------------------------------------------------------------------------

#define MAX_NODES 100000
#define MAX_EDGES 1700000
#define HID 256
#define NGRAPH 2048
#define SCAN_CHUNK 512
#define MAX_SCAN_BLOCKS ((MAX_NODES + SCAN_CHUNK - 1) / SCAN_CHUNK)

__device__ __half g_aggH[(size_t)MAX_NODES * HID];   // agg (fp16, GEMM A)
__device__ __half g_h1h[(size_t)MAX_NODES * HID];    // h1 (fp16)
__device__ __half g_h2h[(size_t)MAX_NODES * HID];    // h2 (fp16)
__device__ __half g_xh[(size_t)MAX_NODES * 128];     // x (fp16)
__device__ float  g_dinv[MAX_NODES];
__device__ float  g_pool[NGRAPH * HID];
__device__ __half g_Wh[256 * 256];                   // W^T fp16 [N][K]
__device__ int    g_cntI[MAX_NODES];
__device__ int    g_rowptr[MAX_NODES + 1];
__device__ int    g_cursor[MAX_NODES];
__device__ uint2  g_edge[MAX_EDGES];                 // {src, norm}
__device__ int    g_partial[MAX_SCAN_BLOCKS];

// ========================= helpers =========================
#define LDMX4(R, ADDR)                                                          \
    asm volatile("ldmatrix.sync.aligned.m8n8.x4.shared.b16 {%0,%1,%2,%3}, [%4];" \
                 : "=r"((R)[0]), "=r"((R)[1]), "=r"((R)[2]), "=r"((R)[3])        \
                 : "r"(ADDR))

#define MMAF16(D, A, B0, B1)                                                    \
    asm volatile("mma.sync.aligned.m16n8k16.row.col.f32.f16.f16.f32 "            \
                 "{%0,%1,%2,%3}, {%4,%5,%6,%7}, {%8,%9}, {%0,%1,%2,%3};"         \
                 : "+f"((D)[0]), "+f"((D)[1]), "+f"((D)[2]), "+f"((D)[3])        \
                 : "r"((A)[0]), "r"((A)[1]), "r"((A)[2]), "r"((A)[3]),           \
                   "r"(B0), "r"(B1))

// ===================== CSR construction =====================
__global__ void k_zero_cnt(int* cnt, int n) {
    int i = blockIdx.x * blockDim.x + threadIdx.x;
    if (i < n) cnt[i] = 0;
}
__global__ void k_count(const int* __restrict__ dst, int* __restrict__ cnt, int nE) {
    int i = blockIdx.x * blockDim.x + threadIdx.x;
    if (i < nE) atomicAdd(&cnt[dst[i]], 1);
}
__global__ void k_scan_p1(const int* __restrict__ cnt, int* __restrict__ partial, int n) {
    __shared__ int s[256];
    int b = blockIdx.x, t = threadIdx.x;
    int base = b * SCAN_CHUNK;
    int i0 = base + t, i1 = base + 256 + t;
    int v = 0;
    if (i0 < n) v += cnt[i0];
    if (i1 < n) v += cnt[i1];
    s[t] = v;
    __syncthreads();
    #pragma unroll
    for (int off = 128; off > 0; off >>= 1) {
        if (t < off) s[t] += s[t + off];
        __syncthreads();
    }
    if (t == 0) partial[b] = s[0];
}
__global__ void k_scan_p2(int* __restrict__ partial, int nb) {
    __shared__ int s[256];
    int t = threadIdx.x;
    int v = (t < nb) ? partial[t] : 0;
    s[t] = v;
    __syncthreads();
    #pragma unroll
    for (int off = 1; off < 256; off <<= 1) {
        int u = (t >= off) ? s[t - off] : 0;
        __syncthreads();
        s[t] += u;
        __syncthreads();
    }
    if (t < nb) partial[t] = s[t] - v;
}
__global__ void k_scan_p3(const int* __restrict__ cnt, const int* __restrict__ partial,
                          int* __restrict__ rowptr, int* __restrict__ cursor,
                          float* __restrict__ dinv, int n) {
    __shared__ int s[256];
    int b = blockIdx.x, t = threadIdx.x;
    int base = b * SCAN_CHUNK;
    int i0 = base + 2 * t, i1 = i0 + 1;
    int c0 = (i0 < n) ? cnt[i0] : 0;
    int c1 = (i1 < n) ? cnt[i1] : 0;
    int pairSum = c0 + c1;
    s[t] = pairSum;
    __syncthreads();
    #pragma unroll
    for (int off = 1; off < 256; off <<= 1) {
        int u = (t >= off) ? s[t - off] : 0;
        __syncthreads();
        s[t] += u;
        __syncthreads();
    }
    int pre = s[t] - pairSum + partial[b];
    if (i0 < n) {
        rowptr[i0] = pre; cursor[i0] = pre;
        dinv[i0] = rsqrtf((float)(c0 + 1));
        if (i0 == n - 1) rowptr[n] = pre + c0;
    }
    if (i1 < n) {
        rowptr[i1] = pre + c0; cursor[i1] = pre + c0;
        dinv[i1] = rsqrtf((float)(c1 + 1));
        if (i1 == n - 1) rowptr[n] = pre + c0 + c1;
    }
}
__global__ void k_fill(const int* __restrict__ src, const int* __restrict__ dst,
                       const float* __restrict__ dinv, int* __restrict__ cursor,
                       uint2* __restrict__ edges, int nE) {
    int i = blockIdx.x * blockDim.x + threadIdx.x;
    if (i >= nE) return;
    int s = src[i], d = dst[i];
    int pos = atomicAdd(&cursor[d], 1);
    float nm = dinv[s] * dinv[d];
    edges[pos] = make_uint2((unsigned)s, __float_as_uint(nm));
}

// ===================== fp32 -> fp16 conversion =====================
__global__ void k_f2h(const float* __restrict__ X, __half* __restrict__ Xh, long total4) {
    long i = blockIdx.x * (long)blockDim.x + threadIdx.x;
    if (i >= total4) return;
    float4 v = ((const float4*)X)[i];
    __half2 h0 = __floats2half2_rn(v.x, v.y);
    __half2 h1 = __floats2half2_rn(v.z, v.w);
    ((uint2*)Xh)[i] = make_uint2(*(uint32_t*)&h0, *(uint32_t*)&h1);
}

// ===================== CSR gather (fp16 in, fp16 out) ==================
__device__ __forceinline__ void acc4h(float4& a, uint2 u, float nm) {
    float2 p0 = __half22float2(*(__half2*)&u.x);
    float2 p1 = __half22float2(*(__half2*)&u.y);
    a.x += nm * p0.x; a.y += nm * p0.y; a.z += nm * p1.x; a.w += nm * p1.y;
}
__device__ __forceinline__ void acc8h(float4& a0, float4& a1, uint4 u, float nm) {
    float2 p0 = __half22float2(*(__half2*)&u.x);
    float2 p1 = __half22float2(*(__half2*)&u.y);
    float2 p2 = __half22float2(*(__half2*)&u.z);
    float2 p3 = __half22float2(*(__half2*)&u.w);
    a0.x += nm * p0.x; a0.y += nm * p0.y; a0.z += nm * p1.x; a0.w += nm * p1.y;
    a1.x += nm * p2.x; a1.y += nm * p2.y; a1.z += nm * p3.x; a1.w += nm * p3.y;
}
__device__ __forceinline__ uint2 pack4h(float4 a) {
    __half2 h0 = __floats2half2_rn(a.x, a.y);
    __half2 h1 = __floats2half2_rn(a.z, a.w);
    return make_uint2(*(uint32_t*)&h0, *(uint32_t*)&h1);
}

// layer 1: 128 cols
__global__ __launch_bounds__(256)
void k_gather128h(const __half* __restrict__ Xh,
                  const int* __restrict__ rowptr, const uint2* __restrict__ edges,
                  const float* __restrict__ dinv, __half* __restrict__ Agg, int n) {
    int node = (blockIdx.x * blockDim.x + threadIdx.x) >> 5;
    if (node >= n) return;
    int lane = threadIdx.x & 31;
    float di = dinv[node];
    float s2 = di * di;
    const uint2* Xv = (const uint2*)Xh;
    float4 a = make_float4(0.f, 0.f, 0.f, 0.f);
    acc4h(a, Xv[(size_t)node * 32 + lane], s2);   // self-loop
    int e = rowptr[node], e1 = rowptr[node + 1];
    for (; e + 4 <= e1; e += 4) {
        uint2 E0 = edges[e],     E1 = edges[e + 1];
        uint2 E2 = edges[e + 2], E3 = edges[e + 3];
        uint2 u0 = Xv[(size_t)E0.x * 32 + lane];
        uint2 u1 = Xv[(size_t)E1.x * 32 + lane];
        uint2 u2 = Xv[(size_t)E2.x * 32 + lane];
        uint2 u3 = Xv[(size_t)E3.x * 32 + lane];
        acc4h(a, u0, __uint_as_float(E0.y));
        acc4h(a, u1, __uint_as_float(E1.y));
        acc4h(a, u2, __uint_as_float(E2.y));
        acc4h(a, u3, __uint_as_float(E3.y));
    }
    for (; e < e1; ++e) {
        uint2 E = edges[e];
        acc4h(a, Xv[(size_t)E.x * 32 + lane], __uint_as_float(E.y));
    }
    __stcs(&((uint2*)Agg)[(size_t)node * 32 + lane], pack4h(a));
}

// layer 2: 256 cols
__global__ __launch_bounds__(256)
void k_gather256h(const __half* __restrict__ H,
                  const int* __restrict__ rowptr, const uint2* __restrict__ edges,
                  const float* __restrict__ dinv, __half* __restrict__ Agg, int n) {
    int node = (blockIdx.x * blockDim.x + threadIdx.x) >> 5;
    if (node >= n) return;
    int lane = threadIdx.x & 31;
    float di = dinv[node];
    float s2 = di * di;
    const uint4* Hv = (const uint4*)H;
    float4 a0 = make_float4(0.f, 0.f, 0.f, 0.f);
    float4 a1 = make_float4(0.f, 0.f, 0.f, 0.f);
    acc8h(a0, a1, Hv[(size_t)node * 32 + lane], s2);
    int e = rowptr[node], e1 = rowptr[node + 1];
    for (; e + 4 <= e1; e += 4) {
        uint2 E0 = edges[e],     E1 = edges[e + 1];
        uint2 E2 = edges[e + 2], E3 = edges[e + 3];
        uint4 u0 = Hv[(size_t)E0.x * 32 + lane];
        uint4 u1 = Hv[(size_t)E1.x * 32 + lane];
        uint4 u2 = Hv[(size_t)E2.x * 32 + lane];
        uint4 u3 = Hv[(size_t)E3.x * 32 + lane];
        acc8h(a0, a1, u0, __uint_as_float(E0.y));
        acc8h(a0, a1, u1, __uint_as_float(E1.y));
        acc8h(a0, a1, u2, __uint_as_float(E2.y));
        acc8h(a0, a1, u3, __uint_as_float(E3.y));
    }
    for (; e < e1; ++e) {
        uint2 E = edges[e];
        acc8h(a0, a1, Hv[(size_t)E.x * 32 + lane], __uint_as_float(E.y));
    }
    uint2 p0 = pack4h(a0), p1 = pack4h(a1);
    __stcs(&((uint4*)Agg)[(size_t)node * 32 + lane], make_uint4(p0.x, p0.y, p1.x, p1.y));
}

// ================= W prep: fp32 [K][256] -> fp16 [256][K] =============
__global__ void k_prep_W(const float* __restrict__ W, __half* __restrict__ Wh, int K) {
    int idx = blockIdx.x * blockDim.x + threadIdx.x;
    if (idx >= K * 256) return;
    int n = idx / K, k = idx % K;
    Wh[idx] = __float2half_rn(W[(size_t)k * 256 + n]);
}

// ===================== tensor-core GEMM (M x K) @ (K x 256) =================
// A fp16 [M][K]; W fp16 pre-transposed [256][K]. C = relu(A@W + bias) fp16.
#define BM 128
#define BN 128
#define BK 32
#define LDS_PAD 40

__global__ __launch_bounds__(256, 3)
void k_gemm_mma(const __half* __restrict__ A, const __half* __restrict__ B,
                const float* __restrict__ bias, __half* __restrict__ C,
                int M, int K) {
    __shared__ __align__(16) __half sA[BM * LDS_PAD];
    __shared__ __align__(16) __half sB[BN * LDS_PAD];

    const int tid = threadIdx.x;
    const int wid = tid >> 5, lane = tid & 31;
    const int warpM = wid & 3;
    const int warpN = wid >> 2;
    const int rowBase = blockIdx.y * BM;
    const int colBase = blockIdx.x * BN;

    float acc[2][8][4];
    #pragma unroll
    for (int i = 0; i < 2; i++)
        #pragma unroll
        for (int j = 0; j < 8; j++)
            #pragma unroll
            for (int q = 0; q < 4; q++) acc[i][j][q] = 0.f;

    const int aRow = warpM * 32 + (lane & 15);
    const int aK   = (lane >> 4) * 8;
    const int bRowBase = warpN * 64 + (lane & 7) + ((lane >> 4) << 3);
    const int bK   = ((lane >> 3) & 1) * 8;

    uint32_t sA_b = (uint32_t)__cvta_generic_to_shared(sA);
    uint32_t sB_b = (uint32_t)__cvta_generic_to_shared(sB);

    const uint4 zero4 = make_uint4(0u, 0u, 0u, 0u);

    for (int k0 = 0; k0 < K; k0 += BK) {
        {
            #pragma unroll
            for (int it = 0; it < 2; ++it) {
                int i = tid + it * 256;
                int r  = i >> 2;
                int c8 = (i & 3) * 8;
                int gr = rowBase + r;
                uint4 v = zero4;
                if (gr < M) v = *(const uint4*)(A + (size_t)gr * K + k0 + c8);
                *(uint4*)&sA[r * LDS_PAD + c8] = v;
            }
        }
        {
            #pragma unroll
            for (int it = 0; it < 2; ++it) {
                int i = tid + it * 256;
                int nn = i >> 2;
                int kq = (i & 3) * 8;
                *(uint4*)&sB[nn * LDS_PAD + kq] =
                    *(const uint4*)(B + (size_t)(colBase + nn) * K + k0 + kq);
            }
        }
        __syncthreads();

        #pragma unroll
        for (int kk = 0; kk < BK; kk += 16) {
            uint32_t aR[2][4];
            #pragma unroll
            for (int mi = 0; mi < 2; ++mi) {
                uint32_t o = (uint32_t)((aRow + mi * 16) * LDS_PAD + kk + aK) * 2;
                LDMX4(aR[mi], sA_b + o);
            }
            #pragma unroll
            for (int nj = 0; nj < 4; ++nj) {
                uint32_t bR[4];
                uint32_t o = (uint32_t)((bRowBase + nj * 16) * LDS_PAD + kk + bK) * 2;
                LDMX4(bR, sB_b + o);
                #pragma unroll
                for (int mi = 0; mi < 2; ++mi) {
                    MMAF16(acc[mi][nj * 2 + 0], aR[mi], bR[0], bR[1]);
                    MMAF16(acc[mi][nj * 2 + 1], aR[mi], bR[2], bR[3]);
                }
            }
        }
        __syncthreads();
    }

    const int erow = rowBase + warpM * 32 + (lane >> 2);
    const int ecol = colBase + warpN * 64 + (lane & 3) * 2;
    #pragma unroll
    for (int mi = 0; mi < 2; ++mi) {
        int r0 = erow + mi * 16;
        #pragma unroll
        for (int nj = 0; nj < 8; ++nj) {
            int c = ecol + nj * 8;
            float b0 = bias[c], b1 = bias[c + 1];
            float v00 = fmaxf(acc[mi][nj][0] + b0, 0.f);
            float v01 = fmaxf(acc[mi][nj][1] + b1, 0.f);
            float v10 = fmaxf(acc[mi][nj][2] + b0, 0.f);
            float v11 = fmaxf(acc[mi][nj][3] + b1, 0.f);
            if (r0 < M)     *(__half2*)(C + (size_t)r0 * 256 + c)       = __floats2half2_rn(v00, v01);
            if (r0 + 8 < M) *(__half2*)(C + (size_t)(r0 + 8) * 256 + c) = __floats2half2_rn(v10, v11);
        }
    }
}

// ============ pooling: sorted-segment mean (fp16 in, fp32 out) =============
__global__ __launch_bounds__(256)
void k_pool_seg(const __half* __restrict__ H, const int* __restrict__ batch,
                float* __restrict__ pool, int n) {
    int g = (blockIdx.x * blockDim.x + threadIdx.x) >> 5;
    if (g >= NGRAPH) return;
    int lane = threadIdx.x & 31;
    int lo = 0, hi = n;
    while (lo < hi) { int mid = (lo + hi) >> 1; if (batch[mid] < g) lo = mid + 1; else hi = mid; }
    int start = lo;
    hi = n;
    while (lo < hi) { int mid = (lo + hi) >> 1; if (batch[mid] < g + 1) lo = mid + 1; else hi = mid; }
    int end = lo;

    float4 a0 = make_float4(0.f, 0.f, 0.f, 0.f);
    float4 a1 = make_float4(0.f, 0.f, 0.f, 0.f);
    const uint4* Hv = (const uint4*)H;
    for (int i = start; i < end; ++i) {
        acc8h(a0, a1, Hv[(size_t)i * 32 + lane], 1.0f);
    }
    float inv = (end > start) ? 1.0f / (float)(end - start) : 0.f;
    a0.x *= inv; a0.y *= inv; a0.z *= inv; a0.w *= inv;
    a1.x *= inv; a1.y *= inv; a1.z *= inv; a1.w *= inv;
    ((float4*)pool)[(size_t)g * 64 + 2 * lane]     = a0;
    ((float4*)pool)[(size_t)g * 64 + 2 * lane + 1] = a1;
}

// ================================ MLP head =================================
__global__ void k_mlp(const float* __restrict__ pool,
                      const float* __restrict__ Wf1, const float* __restrict__ bf1,
                      const float* __restrict__ Wf2, const float* __restrict__ bf2,
                      float* __restrict__ out) {
    int g = blockIdx.x;
    __shared__ float p[HID];
    __shared__ float red[128];
    int t = threadIdx.x;
    p[t]       = pool[g * HID + t];
    p[t + 128] = pool[g * HID + 128 + t];
    __syncthreads();
    float acc = bf1[t];
    #pragma unroll 8
    for (int k = 0; k < HID; k++) acc += p[k] * Wf1[k * 128 + t];
    red[t] = fmaxf(acc, 0.f) * Wf2[t];
    __syncthreads();
    for (int s = 64; s > 0; s >>= 1) {
        if (t < s) red[t] += red[t + s];
        __syncthreads();
    }
    if (t == 0) out[g] = red[0] + bf2[0];
}

// ---------------------------------------------------------------------------
extern "C" void kernel_launch(void* const* d_in, const int* in_sizes, int n_in,
                              void* d_out, int out_size) {
    const float* x   = (const float*)d_in[0];
    const int*   ei  = (const int*)d_in[1];
    const int*   bat = (const int*)d_in[2];
    const float* W1  = (const float*)d_in[3];
    const float* b1  = (const float*)d_in[4];
    const float* W2  = (const float*)d_in[5];
    const float* b2  = (const float*)d_in[6];
    const float* Wf1 = (const float*)d_in[7];
    const float* bf1 = (const float*)d_in[8];
    const float* Wf2 = (const float*)d_in[9];
    const float* bf2 = (const float*)d_in[10];
    float* out = (float*)d_out;

    int n  = in_sizes[0] / 128;
    int nE = in_sizes[1] / 2;
    const int* src = ei;
    const int* dst = ei + nE;

    float *dinv, *pool;
    __half *aggH, *h1h, *h2h, *xh, *Wh;
    int *cntI, *rowptr, *cursor, *partial;
    uint2 *edges;
    cudaGetSymbolAddress((void**)&aggH, g_aggH);
    cudaGetSymbolAddress((void**)&h1h,  g_h1h);
    cudaGetSymbolAddress((void**)&h2h,  g_h2h);
    cudaGetSymbolAddress((void**)&xh,   g_xh);
    cudaGetSymbolAddress((void**)&dinv, g_dinv);
    cudaGetSymbolAddress((void**)&pool, g_pool);
    cudaGetSymbolAddress((void**)&Wh,   g_Wh);
    cudaGetSymbolAddress((void**)&cntI, g_cntI);
    cudaGetSymbolAddress((void**)&rowptr, g_rowptr);
    cudaGetSymbolAddress((void**)&cursor, g_cursor);
    cudaGetSymbolAddress((void**)&edges, g_edge);
    cudaGetSymbolAddress((void**)&partial, g_partial);

    // --- CSR build + x->fp16 ---
    int nb = (n + SCAN_CHUNK - 1) / SCAN_CHUNK;
    k_zero_cnt<<<(n + 255) / 256, 256>>>(cntI, n);
    k_count<<<(nE + 255) / 256, 256>>>(dst, cntI, nE);
    k_scan_p1<<<nb, 256>>>(cntI, partial, n);
    k_scan_p2<<<1, 256>>>(partial, nb);
    k_scan_p3<<<nb, 256>>>(cntI, partial, rowptr, cursor, dinv, n);
    k_fill<<<(nE + 255) / 256, 256>>>(src, dst, dinv, cursor, edges, nE);
    {
        long t4 = (long)n * 32;
        k_f2h<<<(unsigned)((t4 + 255) / 256), 256>>>(x, xh, t4);
    }

    dim3 gemmGrid(2, (n + BM - 1) / BM);
    unsigned gatherBlocks = (unsigned)(((long)n * 32 + 255) / 256);

    // --- layer 1 ---
    k_gather128h<<<gatherBlocks, 256>>>(xh, rowptr, edges, dinv, aggH, n);
    k_prep_W<<<(128 * 256 + 255) / 256, 256>>>(W1, Wh, 128);
    k_gemm_mma<<<gemmGrid, 256>>>(aggH, Wh, b1, h1h, n, 128);

    // --- layer 2 ---
    k_gather256h<<<gatherBlocks, 256>>>(h1h, rowptr, edges, dinv, aggH, n);
    k_prep_W<<<(256 * 256 + 255) / 256, 256>>>(W2, Wh, 256);
    k_gemm_mma<<<gemmGrid, 256>>>(aggH, Wh, b2, h2h, n, 256);

    // --- pooling + MLP head ---
    {
        unsigned poolBlocks = (unsigned)(((long)NGRAPH * 32 + 255) / 256);
        k_pool_seg<<<poolBlocks, 256>>>(h2h, bat, pool, n);
    }
    k_mlp<<<NGRAPH, 128>>>(pool, Wf1, bf1, Wf2, bf2, out);
}

// round 11
// speedup vs baseline: 1.5566x; 1.2016x over previous
#include <cuda_runtime.h>
#include <cuda_fp16.h>
#include <cstdint>

// ---------------------------------------------------------------------------
// GCN: h1 = relu((ÂX)W1 + b1); h2 = relu((Âh1)W2 + b2); mean pool; MLP head.
// CSR gather (fp16, fp32 accum) -> fp16 agg; cp.async double-buffered fp16
// HMMA GEMMs; fused W-prep / f2h / pool+MLP; sorted-segment pooling.
// ---------------------------------------------------------------------------

#define MAX_NODES 100000
#define MAX_EDGES 1700000
#define HID 256
#define NGRAPH 2048
#define SCAN_CHUNK 512
#define MAX_SCAN_BLOCKS ((MAX_NODES + SCAN_CHUNK - 1) / SCAN_CHUNK)

__device__ __half g_aggH[(size_t)MAX_NODES * HID];
__device__ __half g_h1h[(size_t)MAX_NODES * HID];
__device__ __half g_h2h[(size_t)MAX_NODES * HID];
__device__ __half g_xh[(size_t)MAX_NODES * 128];
__device__ float  g_dinv[MAX_NODES];
__device__ __half g_Wh[256 * 256];                   // W^T fp16 [N][K]
__device__ int    g_cntI[MAX_NODES];
__device__ int    g_rowptr[MAX_NODES + 1];
__device__ int    g_cursor[MAX_NODES];
__device__ uint2  g_edge[MAX_EDGES];                 // {src, norm}
__device__ int    g_partial[MAX_SCAN_BLOCKS];

// ========================= helpers =========================
#define LDMX4(R, ADDR)                                                          \
    asm volatile("ldmatrix.sync.aligned.m8n8.x4.shared.b16 {%0,%1,%2,%3}, [%4];" \
                 : "=r"((R)[0]), "=r"((R)[1]), "=r"((R)[2]), "=r"((R)[3])        \
                 : "r"(ADDR))

#define MMAF16(D, A, B0, B1)                                                    \
    asm volatile("mma.sync.aligned.m16n8k16.row.col.f32.f16.f16.f32 "            \
                 "{%0,%1,%2,%3}, {%4,%5,%6,%7}, {%8,%9}, {%0,%1,%2,%3};"         \
                 : "+f"((D)[0]), "+f"((D)[1]), "+f"((D)[2]), "+f"((D)[3])        \
                 : "r"((A)[0]), "r"((A)[1]), "r"((A)[2]), "r"((A)[3]),           \
                   "r"(B0), "r"(B1))

#define CP_ASYNC16(dst, src) \
    asm volatile("cp.async.cg.shared.global [%0], [%1], 16;" :: "r"(dst), "l"(src))
#define CP_COMMIT()  asm volatile("cp.async.commit_group;" ::: "memory")
#define CP_WAIT1()   asm volatile("cp.async.wait_group 1;" ::: "memory")
#define CP_WAIT0()   asm volatile("cp.async.wait_group 0;" ::: "memory")

// ===================== CSR construction =====================
// fused: edge-degree count + x fp32->fp16 conversion
__global__ void k_count_f2h(const int* __restrict__ dst, int* __restrict__ cnt, int nE,
                            int nbCount, const float* __restrict__ X,
                            __half* __restrict__ Xh, long t4) {
    if ((int)blockIdx.x < nbCount) {
        int i = blockIdx.x * 256 + threadIdx.x;
        if (i < nE) atomicAdd(&cnt[dst[i]], 1);
    } else {
        long i = (long)(blockIdx.x - nbCount) * 256 + threadIdx.x;
        if (i < t4) {
            float4 v = ((const float4*)X)[i];
            __half2 h0 = __floats2half2_rn(v.x, v.y);
            __half2 h1 = __floats2half2_rn(v.z, v.w);
            ((uint2*)Xh)[i] = make_uint2(*(uint32_t*)&h0, *(uint32_t*)&h1);
        }
    }
}
__global__ void k_scan_p1(const int* __restrict__ cnt, int* __restrict__ partial, int n) {
    __shared__ int s[256];
    int b = blockIdx.x, t = threadIdx.x;
    int base = b * SCAN_CHUNK;
    int i0 = base + t, i1 = base + 256 + t;
    int v = 0;
    if (i0 < n) v += cnt[i0];
    if (i1 < n) v += cnt[i1];
    s[t] = v;
    __syncthreads();
    #pragma unroll
    for (int off = 128; off > 0; off >>= 1) {
        if (t < off) s[t] += s[t + off];
        __syncthreads();
    }
    if (t == 0) partial[b] = s[0];
}
__global__ void k_scan_p2(int* __restrict__ partial, int nb) {
    __shared__ int s[256];
    int t = threadIdx.x;
    int v = (t < nb) ? partial[t] : 0;
    s[t] = v;
    __syncthreads();
    #pragma unroll
    for (int off = 1; off < 256; off <<= 1) {
        int u = (t >= off) ? s[t - off] : 0;
        __syncthreads();
        s[t] += u;
        __syncthreads();
    }
    if (t < nb) partial[t] = s[t] - v;
}
__global__ void k_scan_p3(const int* __restrict__ cnt, const int* __restrict__ partial,
                          int* __restrict__ rowptr, int* __restrict__ cursor,
                          float* __restrict__ dinv, int n) {
    __shared__ int s[256];
    int b = blockIdx.x, t = threadIdx.x;
    int base = b * SCAN_CHUNK;
    int i0 = base + 2 * t, i1 = i0 + 1;
    int c0 = (i0 < n) ? cnt[i0] : 0;
    int c1 = (i1 < n) ? cnt[i1] : 0;
    int pairSum = c0 + c1;
    s[t] = pairSum;
    __syncthreads();
    #pragma unroll
    for (int off = 1; off < 256; off <<= 1) {
        int u = (t >= off) ? s[t - off] : 0;
        __syncthreads();
        s[t] += u;
        __syncthreads();
    }
    int pre = s[t] - pairSum + partial[b];
    if (i0 < n) {
        rowptr[i0] = pre; cursor[i0] = pre;
        dinv[i0] = rsqrtf((float)(c0 + 1));
        if (i0 == n - 1) rowptr[n] = pre + c0;
    }
    if (i1 < n) {
        rowptr[i1] = pre + c0; cursor[i1] = pre + c0;
        dinv[i1] = rsqrtf((float)(c1 + 1));
        if (i1 == n - 1) rowptr[n] = pre + c0 + c1;
    }
}
__global__ void k_fill(const int* __restrict__ src, const int* __restrict__ dst,
                       const float* __restrict__ dinv, int* __restrict__ cursor,
                       uint2* __restrict__ edges, int nE) {
    int i = blockIdx.x * blockDim.x + threadIdx.x;
    if (i >= nE) return;
    int s = src[i], d = dst[i];
    int pos = atomicAdd(&cursor[d], 1);
    float nm = dinv[s] * dinv[d];
    edges[pos] = make_uint2((unsigned)s, __float_as_uint(nm));
}

// ===================== CSR gather (fp16 in, fp16 out) ==================
__device__ __forceinline__ void acc4h(float4& a, uint2 u, float nm) {
    float2 p0 = __half22float2(*(__half2*)&u.x);
    float2 p1 = __half22float2(*(__half2*)&u.y);
    a.x += nm * p0.x; a.y += nm * p0.y; a.z += nm * p1.x; a.w += nm * p1.y;
}
__device__ __forceinline__ void acc8h(float4& a0, float4& a1, uint4 u, float nm) {
    float2 p0 = __half22float2(*(__half2*)&u.x);
    float2 p1 = __half22float2(*(__half2*)&u.y);
    float2 p2 = __half22float2(*(__half2*)&u.z);
    float2 p3 = __half22float2(*(__half2*)&u.w);
    a0.x += nm * p0.x; a0.y += nm * p0.y; a0.z += nm * p1.x; a0.w += nm * p1.y;
    a1.x += nm * p2.x; a1.y += nm * p2.y; a1.z += nm * p3.x; a1.w += nm * p3.y;
}
__device__ __forceinline__ uint2 pack4h(float4 a) {
    __half2 h0 = __floats2half2_rn(a.x, a.y);
    __half2 h1 = __floats2half2_rn(a.z, a.w);
    return make_uint2(*(uint32_t*)&h0, *(uint32_t*)&h1);
}
__device__ __forceinline__ void prep_w_tail(const float* __restrict__ W,
                                            __half* __restrict__ Wh, int K,
                                            int blockOff) {
    int idx = ((int)blockIdx.x - blockOff) * 256 + threadIdx.x;
    if (idx >= K * 256) return;
    int n = idx / K, k = idx % K;
    Wh[idx] = __float2half_rn(W[(size_t)k * 256 + n]);
}

// layer 1: 128 cols; tail blocks do W1 prep
__global__ __launch_bounds__(256)
void k_gather128h(const __half* __restrict__ Xh,
                  const int* __restrict__ rowptr, const uint2* __restrict__ edges,
                  const float* __restrict__ dinv, __half* __restrict__ Agg, int n,
                  int gatherBlocks, const float* __restrict__ W, __half* __restrict__ Wh) {
    if ((int)blockIdx.x >= gatherBlocks) {
        prep_w_tail(W, Wh, 128, gatherBlocks);
        return;
    }
    int node = (blockIdx.x * 256 + threadIdx.x) >> 5;
    if (node >= n) return;
    int lane = threadIdx.x & 31;
    float di = dinv[node];
    float s2 = di * di;
    const uint2* Xv = (const uint2*)Xh;
    float4 a = make_float4(0.f, 0.f, 0.f, 0.f);
    acc4h(a, Xv[(size_t)node * 32 + lane], s2);
    int e = rowptr[node], e1 = rowptr[node + 1];
    for (; e + 4 <= e1; e += 4) {
        uint2 E0 = edges[e],     E1 = edges[e + 1];
        uint2 E2 = edges[e + 2], E3 = edges[e + 3];
        uint2 u0 = Xv[(size_t)E0.x * 32 + lane];
        uint2 u1 = Xv[(size_t)E1.x * 32 + lane];
        uint2 u2 = Xv[(size_t)E2.x * 32 + lane];
        uint2 u3 = Xv[(size_t)E3.x * 32 + lane];
        acc4h(a, u0, __uint_as_float(E0.y));
        acc4h(a, u1, __uint_as_float(E1.y));
        acc4h(a, u2, __uint_as_float(E2.y));
        acc4h(a, u3, __uint_as_float(E3.y));
    }
    for (; e < e1; ++e) {
        uint2 E = edges[e];
        acc4h(a, Xv[(size_t)E.x * 32 + lane], __uint_as_float(E.y));
    }
    __stcs(&((uint2*)Agg)[(size_t)node * 32 + lane], pack4h(a));
}

// layer 2: 256 cols; tail blocks do W2 prep
__global__ __launch_bounds__(256)
void k_gather256h(const __half* __restrict__ H,
                  const int* __restrict__ rowptr, const uint2* __restrict__ edges,
                  const float* __restrict__ dinv, __half* __restrict__ Agg, int n,
                  int gatherBlocks, const float* __restrict__ W, __half* __restrict__ Wh) {
    if ((int)blockIdx.x >= gatherBlocks) {
        prep_w_tail(W, Wh, 256, gatherBlocks);
        return;
    }
    int node = (blockIdx.x * 256 + threadIdx.x) >> 5;
    if (node >= n) return;
    int lane = threadIdx.x & 31;
    float di = dinv[node];
    float s2 = di * di;
    const uint4* Hv = (const uint4*)H;
    float4 a0 = make_float4(0.f, 0.f, 0.f, 0.f);
    float4 a1 = make_float4(0.f, 0.f, 0.f, 0.f);
    acc8h(a0, a1, Hv[(size_t)node * 32 + lane], s2);
    int e = rowptr[node], e1 = rowptr[node + 1];
    for (; e + 4 <= e1; e += 4) {
        uint2 E0 = edges[e],     E1 = edges[e + 1];
        uint2 E2 = edges[e + 2], E3 = edges[e + 3];
        uint4 u0 = Hv[(size_t)E0.x * 32 + lane];
        uint4 u1 = Hv[(size_t)E1.x * 32 + lane];
        uint4 u2 = Hv[(size_t)E2.x * 32 + lane];
        uint4 u3 = Hv[(size_t)E3.x * 32 + lane];
        acc8h(a0, a1, u0, __uint_as_float(E0.y));
        acc8h(a0, a1, u1, __uint_as_float(E1.y));
        acc8h(a0, a1, u2, __uint_as_float(E2.y));
        acc8h(a0, a1, u3, __uint_as_float(E3.y));
    }
    for (; e < e1; ++e) {
        uint2 E = edges[e];
        acc8h(a0, a1, Hv[(size_t)E.x * 32 + lane], __uint_as_float(E.y));
    }
    uint2 p0 = pack4h(a0), p1 = pack4h(a1);
    __stcs(&((uint4*)Agg)[(size_t)node * 32 + lane], make_uint4(p0.x, p0.y, p1.x, p1.y));
}

// ===================== tensor-core GEMM (M x K) @ (K x 256) =================
// A fp16 [M][K]; W fp16 pre-transposed [256][K]. C = relu(A@W + bias) fp16.
// cp.async double-buffered pipeline.
#define BM 128
#define BN 128
#define BK 32
#define LDS_PAD 40

__global__ __launch_bounds__(256, 3)
void k_gemm_mma(const __half* __restrict__ A, const __half* __restrict__ B,
                const float* __restrict__ bias, __half* __restrict__ C,
                int M, int K) {
    __shared__ __align__(16) __half sA[2][BM * LDS_PAD];
    __shared__ __align__(16) __half sB[2][BN * LDS_PAD];

    const int tid = threadIdx.x;
    const int wid = tid >> 5, lane = tid & 31;
    const int warpM = wid & 3;
    const int warpN = wid >> 2;
    const int rowBase = blockIdx.y * BM;
    const int colBase = blockIdx.x * BN;

    float acc[2][8][4];
    #pragma unroll
    for (int i = 0; i < 2; i++)
        #pragma unroll
        for (int j = 0; j < 8; j++)
            #pragma unroll
            for (int q = 0; q < 4; q++) acc[i][j][q] = 0.f;

    const int aRow = warpM * 32 + (lane & 15);
    const int aK   = (lane >> 4) * 8;
    const int bRowBase = warpN * 64 + (lane & 7) + ((lane >> 4) << 3);
    const int bK   = ((lane >> 3) & 1) * 8;

    uint32_t sA_b = (uint32_t)__cvta_generic_to_shared(sA);
    uint32_t sB_b = (uint32_t)__cvta_generic_to_shared(sB);
    const uint32_t STAGE = BM * LDS_PAD * 2;   // bytes per stage

    // per-thread load coords (2 x 16B per tensor per stage)
    const int lr  = tid >> 2;          // 0..63 (two iters -> 0..127)
    const int lc8 = (tid & 3) * 8;

    auto issueLoads = [&](int k0, int st) {
        #pragma unroll
        for (int it = 0; it < 2; ++it) {
            int r = lr + it * 64;
            int gr = rowBase + r; if (gr >= M) gr = M - 1;   // dup row; unused output
            const __half* srcA = A + (size_t)gr * K + k0 + lc8;
            CP_ASYNC16(sA_b + st * STAGE + (uint32_t)(r * LDS_PAD + lc8) * 2, srcA);
            const __half* srcB = B + (size_t)(colBase + r) * K + k0 + lc8;
            CP_ASYNC16(sB_b + st * STAGE + (uint32_t)(r * LDS_PAD + lc8) * 2, srcB);
        }
        CP_COMMIT();
    };

    const int nCh = K >> 5;
    issueLoads(0, 0);
    for (int c = 0; c < nCh; ++c) {
        int st = c & 1;
        if (c + 1 < nCh) {
            issueLoads((c + 1) << 5, st ^ 1);
            CP_WAIT1();
        } else {
            CP_WAIT0();
        }
        __syncthreads();

        uint32_t baseA = sA_b + st * STAGE;
        uint32_t baseB = sB_b + st * STAGE;
        #pragma unroll
        for (int kk = 0; kk < BK; kk += 16) {
            uint32_t aR[2][4];
            #pragma unroll
            for (int mi = 0; mi < 2; ++mi) {
                uint32_t o = (uint32_t)((aRow + mi * 16) * LDS_PAD + kk + aK) * 2;
                LDMX4(aR[mi], baseA + o);
            }
            #pragma unroll
            for (int nj = 0; nj < 4; ++nj) {
                uint32_t bR[4];
                uint32_t o = (uint32_t)((bRowBase + nj * 16) * LDS_PAD + kk + bK) * 2;
                LDMX4(bR, baseB + o);
                #pragma unroll
                for (int mi = 0; mi < 2; ++mi) {
                    MMAF16(acc[mi][nj * 2 + 0], aR[mi], bR[0], bR[1]);
                    MMAF16(acc[mi][nj * 2 + 1], aR[mi], bR[2], bR[3]);
                }
            }
        }
        __syncthreads();
    }

    const int erow = rowBase + warpM * 32 + (lane >> 2);
    const int ecol = colBase + warpN * 64 + (lane & 3) * 2;
    #pragma unroll
    for (int mi = 0; mi < 2; ++mi) {
        int r0 = erow + mi * 16;
        #pragma unroll
        for (int nj = 0; nj < 8; ++nj) {
            int c = ecol + nj * 8;
            float b0 = bias[c], b1 = bias[c + 1];
            float v00 = fmaxf(acc[mi][nj][0] + b0, 0.f);
            float v01 = fmaxf(acc[mi][nj][1] + b1, 0.f);
            float v10 = fmaxf(acc[mi][nj][2] + b0, 0.f);
            float v11 = fmaxf(acc[mi][nj][3] + b1, 0.f);
            if (r0 < M)     *(__half2*)(C + (size_t)r0 * 256 + c)       = __floats2half2_rn(v00, v01);
            if (r0 + 8 < M) *(__half2*)(C + (size_t)(r0 + 8) * 256 + c) = __floats2half2_rn(v10, v11);
        }
    }
}

// ============ fused pooling + MLP head: one block per graph ============
__global__ __launch_bounds__(128)
void k_pool_mlp(const __half* __restrict__ H, const int* __restrict__ batch,
                const float* __restrict__ Wf1, const float* __restrict__ bf1,
                const float* __restrict__ Wf2, const float* __restrict__ bf2,
                float* __restrict__ out, int n) {
    int g = blockIdx.x;
    int t = threadIdx.x;   // 128
    __shared__ float p[HID];
    __shared__ float red[128];

    int lo = 0, hi = n;
    while (lo < hi) { int mid = (lo + hi) >> 1; if (batch[mid] < g) lo = mid + 1; else hi = mid; }
    int start = lo;
    hi = n;
    while (lo < hi) { int mid = (lo + hi) >> 1; if (batch[mid] < g + 1) lo = mid + 1; else hi = mid; }
    int end = lo;

    // mean over segment: thread t covers cols 2t, 2t+1
    float2 a = make_float2(0.f, 0.f);
    const uint32_t* Hu = (const uint32_t*)H;
    for (int i = start; i < end; ++i) {
        uint32_t u = Hu[(size_t)i * 128 + t];
        float2 v = __half22float2(*(__half2*)&u);
        a.x += v.x; a.y += v.y;
    }
    float inv = (end > start) ? 1.0f / (float)(end - start) : 0.f;
    p[2 * t]     = a.x * inv;
    p[2 * t + 1] = a.y * inv;
    __syncthreads();

    float acc = bf1[t];
    #pragma unroll 8
    for (int k = 0; k < HID; k++) acc += p[k] * Wf1[k * 128 + t];
    red[t] = fmaxf(acc, 0.f) * Wf2[t];
    __syncthreads();
    for (int s = 64; s > 0; s >>= 1) {
        if (t < s) red[t] += red[t + s];
        __syncthreads();
    }
    if (t == 0) out[g] = red[0] + bf2[0];
}

// ---------------------------------------------------------------------------
extern "C" void kernel_launch(void* const* d_in, const int* in_sizes, int n_in,
                              void* d_out, int out_size) {
    const float* x   = (const float*)d_in[0];
    const int*   ei  = (const int*)d_in[1];
    const int*   bat = (const int*)d_in[2];
    const float* W1  = (const float*)d_in[3];
    const float* b1  = (const float*)d_in[4];
    const float* W2  = (const float*)d_in[5];
    const float* b2  = (const float*)d_in[6];
    const float* Wf1 = (const float*)d_in[7];
    const float* bf1 = (const float*)d_in[8];
    const float* Wf2 = (const float*)d_in[9];
    const float* bf2 = (const float*)d_in[10];
    float* out = (float*)d_out;

    int n  = in_sizes[0] / 128;
    int nE = in_sizes[1] / 2;
    const int* src = ei;
    const int* dst = ei + nE;

    float *dinv;
    __half *aggH, *h1h, *h2h, *xh, *Wh;
    int *cntI, *rowptr, *cursor, *partial;
    uint2 *edges;
    cudaGetSymbolAddress((void**)&aggH, g_aggH);
    cudaGetSymbolAddress((void**)&h1h,  g_h1h);
    cudaGetSymbolAddress((void**)&h2h,  g_h2h);
    cudaGetSymbolAddress((void**)&xh,   g_xh);
    cudaGetSymbolAddress((void**)&dinv, g_dinv);
    cudaGetSymbolAddress((void**)&Wh,   g_Wh);
    cudaGetSymbolAddress((void**)&cntI, g_cntI);
    cudaGetSymbolAddress((void**)&rowptr, g_rowptr);
    cudaGetSymbolAddress((void**)&cursor, g_cursor);
    cudaGetSymbolAddress((void**)&edges, g_edge);
    cudaGetSymbolAddress((void**)&partial, g_partial);

    // --- CSR build + x->fp16 ---
    int nb = (n + SCAN_CHUNK - 1) / SCAN_CHUNK;
    cudaMemsetAsync(cntI, 0, (size_t)n * sizeof(int));
    {
        int nbCount = (nE + 255) / 256;
        long t4 = (long)n * 32;
        int nbF2h = (int)((t4 + 255) / 256);
        k_count_f2h<<<nbCount + nbF2h, 256>>>(dst, cntI, nE, nbCount, x, xh, t4);
    }
    k_scan_p1<<<nb, 256>>>(cntI, partial, n);
    k_scan_p2<<<1, 256>>>(partial, nb);
    k_scan_p3<<<nb, 256>>>(cntI, partial, rowptr, cursor, dinv, n);
    k_fill<<<(nE + 255) / 256, 256>>>(src, dst, dinv, cursor, edges, nE);

    dim3 gemmGrid(2, (n + BM - 1) / BM);
    int gatherBlocks = (int)(((long)n * 32 + 255) / 256);

    // --- layer 1 (gather + W1 prep fused) ---
    k_gather128h<<<gatherBlocks + 128, 256>>>(xh, rowptr, edges, dinv, aggH, n,
                                              gatherBlocks, W1, Wh);
    k_gemm_mma<<<gemmGrid, 256>>>(aggH, Wh, b1, h1h, n, 128);

    // --- layer 2 (gather + W2 prep fused) ---
    k_gather256h<<<gatherBlocks + 256, 256>>>(h1h, rowptr, edges, dinv, aggH, n,
                                              gatherBlocks, W2, Wh);
    k_gemm_mma<<<gemmGrid, 256>>>(aggH, Wh, b2, h2h, n, 256);

    // --- fused pooling + MLP head ---
    k_pool_mlp<<<NGRAPH, 128>>>(h2h, bat, Wf1, bf1, Wf2, bf2, out, n);
}